// round 12
// baseline (speedup 1.0000x reference)
#include <cuda_runtime.h>
#include <cuda_bf16.h>
#include <cstdint>

#define NE 8
#define HD 1024
#define FD 2048
#define NT 8192
#define NSLOT (NT*2)

// ---------------- device scratch ----------------
__device__ int   d_count[NE];
__device__ int   d_offset[NE];
__device__ int   d_etok[NE * NT];
__device__ int   d_slot[NSLOT];
__device__ float d_tw[NSLOT];

__device__ __nv_bfloat16 d_xh[(size_t)NT * HD];
__device__ __nv_bfloat16 d_xl[(size_t)NT * HD];
__device__ __nv_bfloat16 d_wgh[(size_t)NE * HD * FD];   // [E][F][H] K-major (n rows, k cols)
__device__ __nv_bfloat16 d_wgl[(size_t)NE * HD * FD];
__device__ __nv_bfloat16 d_wuh[(size_t)NE * HD * FD];
__device__ __nv_bfloat16 d_wul[(size_t)NE * HD * FD];
__device__ __nv_bfloat16 d_wdh[(size_t)NE * FD * HD];   // [E][H][F] K-major
__device__ __nv_bfloat16 d_wdl[(size_t)NE * FD * HD];
__device__ __nv_bfloat16 d_gh[(size_t)NSLOT * FD];
__device__ __nv_bfloat16 d_gl[(size_t)NSLOT * FD];
__device__ float d_y[(size_t)NSLOT * HD];

// ---------------- helpers ----------------
__device__ __forceinline__ void mma16816(float* d, const uint32_t* a, const uint32_t* b) {
    asm volatile("mma.sync.aligned.m16n8k16.row.col.f32.bf16.bf16.f32 "
        "{%0,%1,%2,%3}, {%4,%5,%6,%7}, {%8,%9}, {%0,%1,%2,%3};"
        : "+f"(d[0]), "+f"(d[1]), "+f"(d[2]), "+f"(d[3])
        : "r"(a[0]), "r"(a[1]), "r"(a[2]), "r"(a[3]), "r"(b[0]), "r"(b[1]));
}
__device__ __forceinline__ uint32_t pack2(__nv_bfloat16 a, __nv_bfloat16 b) {
    return (uint32_t)__bfloat16_as_ushort(a) | ((uint32_t)__bfloat16_as_ushort(b) << 16);
}
__device__ __forceinline__ void split_bf16(float v, __nv_bfloat16& h, __nv_bfloat16& l) {
    h = __float2bfloat16(v);
    l = __float2bfloat16(v - __bfloat162float(h));
}

#define ARS 40           // bf16 tile row stride in bytes (16 k * 2B + 8 pad)
#define TILE_BYTES 2560  // 64 rows * 40
#define LOFF TILE_BYTES  // lo tile follows hi tile within an operand pair
#define OPBYTES (2 * TILE_BYTES)   // 5120 per operand (hi+lo)

// ---------------- routing (proven R1) ----------------
__global__ void zero_counts_kernel() {
    if (threadIdx.x < NE) d_count[threadIdx.x] = 0;
}
__global__ void scan_kernel() {
    int off = 0;
    for (int e = 0; e < NE; e++) { d_offset[e] = off; off += d_count[e]; }
}
__global__ void remap_kernel() {
    int e = blockIdx.x;
    int n = d_count[e], off = d_offset[e];
    for (int p = threadIdx.x; p < n; p += blockDim.x)
        d_slot[d_etok[e * NT + p]] = off + p;
}

__global__ __launch_bounds__(256) void router_kernel(
    const float* __restrict__ x, const float* __restrict__ gw,
    float* __restrict__ logits_out)
{
    __shared__ float gws[NE * HD];
    for (int i = threadIdx.x; i < NE * HD; i += blockDim.x) gws[i] = gw[i];
    __syncthreads();

    int warp = threadIdx.x >> 5, lane = threadIdx.x & 31;
    int t = blockIdx.x * 8 + warp;
    if (t >= NT) return;

    const float* xr = x + (size_t)t * HD;
    float acc[NE];
#pragma unroll
    for (int e = 0; e < NE; e++) acc[e] = 0.f;
    for (int h = lane * 4; h < HD; h += 128) {
        float4 xv = *(const float4*)(xr + h);
#pragma unroll
        for (int e = 0; e < NE; e++) {
            float4 wv = *(const float4*)(&gws[e * HD + h]);
            acc[e] += xv.x * wv.x + xv.y * wv.y + xv.z * wv.z + xv.w * wv.w;
        }
    }
#pragma unroll
    for (int e = 0; e < NE; e++)
        for (int o = 16; o > 0; o >>= 1)
            acc[e] += __shfl_xor_sync(0xffffffffu, acc[e], o);

    if (lane == 0) {
        if (logits_out) {
#pragma unroll
            for (int e = 0; e < NE; e++) logits_out[(size_t)t * NE + e] = acc[e];
        }
        float m = acc[0];
#pragma unroll
        for (int e = 1; e < NE; e++) m = fmaxf(m, acc[e]);
        float p[NE];
#pragma unroll
        for (int e = 0; e < NE; e++) p[e] = expf(acc[e] - m);
        int i1 = 0;
#pragma unroll
        for (int e = 1; e < NE; e++) if (p[e] > p[i1]) i1 = e;
        int i2 = (i1 == 0) ? 1 : 0;
#pragma unroll
        for (int e = 0; e < NE; e++) if (e != i1 && p[e] > p[i2]) i2 = e;
        float s2 = p[i1] + p[i2];
        d_tw[t * 2 + 0] = p[i1] / s2;
        d_tw[t * 2 + 1] = p[i2] / s2;
        int pos = atomicAdd(&d_count[i1], 1);
        d_etok[i1 * NT + pos] = t * 2 + 0;
        pos = atomicAdd(&d_count[i2], 1);
        d_etok[i2 * NT + pos] = t * 2 + 1;
    }
}

// ---------------- prep: x split (device arrays referenced in device code ONLY) ----------------
__global__ __launch_bounds__(256) void convert_x_kernel(const float* __restrict__ x) {
    size_t i4 = ((size_t)blockIdx.x * blockDim.x + threadIdx.x) * 4;
    if (i4 >= (size_t)NT * HD) return;
    float4 v = *(const float4*)(x + i4);
    __nv_bfloat16 h0, l0, h1, l1, h2, l2, h3, l3;
    split_bf16(v.x, h0, l0); split_bf16(v.y, h1, l1);
    split_bf16(v.z, h2, l2); split_bf16(v.w, h3, l3);
    uint2 ph, pl;
    ph.x = pack2(h0, h1); ph.y = pack2(h2, h3);
    pl.x = pack2(l0, l1); pl.y = pack2(l2, l3);
    *(uint2*)(d_xh + i4) = ph;
    *(uint2*)(d_xl + i4) = pl;
}

// prep: transpose + split. W [E][R][C] fp32 -> out [E][C][R] bf16 hi/lo.
// Destination selected IN DEVICE CODE (never pass __device__ symbols from host!).
__global__ __launch_bounds__(256) void transpose_split_kernel(
    const float* __restrict__ W, int which, int R, int C)
{
    __nv_bfloat16* oh;
    __nv_bfloat16* ol;
    if (which == 0)      { oh = d_wgh; ol = d_wgl; }
    else if (which == 1) { oh = d_wuh; ol = d_wul; }
    else                 { oh = d_wdh; ol = d_wdl; }

    __shared__ float t[32][33];
    int e = blockIdx.z;
    const float* w = W + (size_t)e * R * C;
    __nv_bfloat16* ph = oh + (size_t)e * R * C;
    __nv_bfloat16* pl = ol + (size_t)e * R * C;
    int c0 = blockIdx.x * 32, r0 = blockIdx.y * 32;
    int tx = threadIdx.x, ty = threadIdx.y;
#pragma unroll
    for (int i = 0; i < 4; i++)
        t[ty + 8 * i][tx] = w[(size_t)(r0 + ty + 8 * i) * C + c0 + tx];
    __syncthreads();
#pragma unroll
    for (int i = 0; i < 4; i++) {
        float v = t[tx][ty + 8 * i];   // = W[r0+tx][c0+ty+8i]
        __nv_bfloat16 h, l;
        split_bf16(v, h, l);
        size_t o = (size_t)(c0 + ty + 8 * i) * R + r0 + tx;
        ph[o] = h; pl[o] = l;
    }
}

// ---------------- stage A: G = silu(X Wg)*(X Wu), pipelined mma.sync ----------------
// CTA 64m x 64n, BK=16. Double-buffered smem + register prefetch, one sync per chunk.
__global__ __launch_bounds__(256) void gemm_gu_mma(void)
{
    __shared__ __align__(16) char sbuf[2][3 * OPBYTES];
    __shared__ int toks[64];

    int e = blockIdx.z;
    int n = d_count[e];
    int m0 = blockIdx.y * 64;
    if (m0 >= n) return;
    int off = d_offset[e];
    int n0 = blockIdx.x * 64;
    int rows = min(64, n - m0);

    int tid = threadIdx.x, lane = tid & 31, wid = tid >> 5;
    if (tid < 64) toks[tid] = d_etok[e * NT + m0 + min(tid, rows - 1)] >> 1;
    __syncthreads();

    const __nv_bfloat16* wgh = d_wgh + (size_t)e * FD * HD;
    const __nv_bfloat16* wgl = d_wgl + (size_t)e * FD * HD;
    const __nv_bfloat16* wuh = d_wuh + (size_t)e * FD * HD;
    const __nv_bfloat16* wul = d_wul + (size_t)e * FD * HD;

    int arow = tid >> 2, akq = tid & 3;   // 64 rows x 4 k-quads (uint2 = 4 k's)
    size_t aoff = (size_t)toks[arow] * HD + akq * 4;
    size_t boff = (size_t)(n0 + arow) * HD + akq * 4;

    uint2 r_[6];
    auto gload = [&](int ci) {
        int k0 = ci * 16;
        r_[0] = *(const uint2*)(d_xh + aoff + k0);
        r_[1] = *(const uint2*)(d_xl + aoff + k0);
        r_[2] = *(const uint2*)(wgh + boff + k0);
        r_[3] = *(const uint2*)(wgl + boff + k0);
        r_[4] = *(const uint2*)(wuh + boff + k0);
        r_[5] = *(const uint2*)(wul + boff + k0);
    };
    auto gstore = [&](int buf) {
        char* bb = sbuf[buf];
        uint32_t o = arow * ARS + akq * 8;
        *(uint2*)(bb + o) = r_[0];
        *(uint2*)(bb + LOFF + o) = r_[1];
        *(uint2*)(bb + OPBYTES + o) = r_[2];
        *(uint2*)(bb + OPBYTES + LOFF + o) = r_[3];
        *(uint2*)(bb + 2 * OPBYTES + o) = r_[4];
        *(uint2*)(bb + 2 * OPBYTES + LOFF + o) = r_[5];
    };

    int fr = lane >> 2, fc = lane & 3;
    int wm = (wid & 3) * 16, wn = (wid >> 2) * 32;

    float cg[4][4], cu[4][4];
#pragma unroll
    for (int j = 0; j < 4; j++)
#pragma unroll
        for (int q = 0; q < 4; q++) { cg[j][q] = 0.f; cu[j][q] = 0.f; }

    auto compute = [&](int buf) {
        const char* sA = sbuf[buf];
        const char* sBg = sbuf[buf] + OPBYTES;
        const char* sBu = sbuf[buf] + 2 * OPBYTES;
        uint32_t ah[4], al[4];
        int ab = (wm + fr) * ARS + fc * 4;
        ah[0] = *(const uint32_t*)(sA + ab);
        ah[1] = *(const uint32_t*)(sA + ab + 8 * ARS);
        ah[2] = *(const uint32_t*)(sA + ab + 16);
        ah[3] = *(const uint32_t*)(sA + ab + 8 * ARS + 16);
        al[0] = *(const uint32_t*)(sA + LOFF + ab);
        al[1] = *(const uint32_t*)(sA + LOFF + ab + 8 * ARS);
        al[2] = *(const uint32_t*)(sA + LOFF + ab + 16);
        al[3] = *(const uint32_t*)(sA + LOFF + ab + 8 * ARS + 16);
#pragma unroll
        for (int j = 0; j < 4; j++) {
            int bb = (wn + j * 8 + fr) * ARS + fc * 4;
            uint32_t bh[2], bl[2];
            bh[0] = *(const uint32_t*)(sBg + bb);
            bh[1] = *(const uint32_t*)(sBg + bb + 16);
            bl[0] = *(const uint32_t*)(sBg + LOFF + bb);
            bl[1] = *(const uint32_t*)(sBg + LOFF + bb + 16);
            mma16816(cg[j], ah, bh);
            mma16816(cg[j], al, bh);
            mma16816(cg[j], ah, bl);
            bh[0] = *(const uint32_t*)(sBu + bb);
            bh[1] = *(const uint32_t*)(sBu + bb + 16);
            bl[0] = *(const uint32_t*)(sBu + LOFF + bb);
            bl[1] = *(const uint32_t*)(sBu + LOFF + bb + 16);
            mma16816(cu[j], ah, bh);
            mma16816(cu[j], al, bh);
            mma16816(cu[j], ah, bl);
        }
    };

    const int NC = HD / 16;  // 64
    gload(0); gstore(0); gload(1);
    __syncthreads();
    for (int ci = 0; ci < NC; ci++) {
        compute(ci & 1);
        if (ci + 1 < NC) {
            gstore((ci + 1) & 1);
            if (ci + 2 < NC) gload(ci + 2);
            __syncthreads();
        }
    }

    // epilogue: silu(g)*u -> bf16 hi/lo
#pragma unroll
    for (int h = 0; h < 2; h++) {
        int row = wm + fr + h * 8;
        if (row < rows) {
            size_t rb = (size_t)(off + m0 + row) * FD + n0 + wn + fc * 2;
#pragma unroll
            for (int j = 0; j < 4; j++) {
                float g0 = cg[j][h * 2 + 0], g1 = cg[j][h * 2 + 1];
                float u0 = cu[j][h * 2 + 0], u1 = cu[j][h * 2 + 1];
                float v0 = g0 / (1.f + expf(-g0)) * u0;
                float v1 = g1 / (1.f + expf(-g1)) * u1;
                __nv_bfloat16 h0, l0, h1, l1;
                split_bf16(v0, h0, l0);
                split_bf16(v1, h1, l1);
                *(uint32_t*)(d_gh + rb + j * 8) = pack2(h0, h1);
                *(uint32_t*)(d_gl + rb + j * 8) = pack2(l0, l1);
            }
        }
    }
}

// ---------------- stage B: Y = G @ Wd, pipelined mma.sync ----------------
__global__ __launch_bounds__(256) void gemm_d_mma(void)
{
    __shared__ __align__(16) char sbuf[2][2 * OPBYTES];

    int e = blockIdx.z;
    int n = d_count[e];
    int m0 = blockIdx.y * 64;
    if (m0 >= n) return;
    int off = d_offset[e];
    int n0 = blockIdx.x * 64;
    int rows = min(64, n - m0);

    int tid = threadIdx.x, lane = tid & 31, wid = tid >> 5;
    const __nv_bfloat16* wdh = d_wdh + (size_t)e * HD * FD;
    const __nv_bfloat16* wdl = d_wdl + (size_t)e * HD * FD;

    int arow = tid >> 2, akq = tid & 3;
    int ar = min(arow, rows - 1);
    size_t aoff = (size_t)(off + m0 + ar) * FD + akq * 4;
    size_t boff = (size_t)(n0 + arow) * FD + akq * 4;

    uint2 r_[4];
    auto gload = [&](int ci) {
        int k0 = ci * 16;
        r_[0] = *(const uint2*)(d_gh + aoff + k0);
        r_[1] = *(const uint2*)(d_gl + aoff + k0);
        r_[2] = *(const uint2*)(wdh + boff + k0);
        r_[3] = *(const uint2*)(wdl + boff + k0);
    };
    auto gstore = [&](int buf) {
        char* bb = sbuf[buf];
        uint32_t o = arow * ARS + akq * 8;
        *(uint2*)(bb + o) = r_[0];
        *(uint2*)(bb + LOFF + o) = r_[1];
        *(uint2*)(bb + OPBYTES + o) = r_[2];
        *(uint2*)(bb + OPBYTES + LOFF + o) = r_[3];
    };

    int fr = lane >> 2, fc = lane & 3;
    int wm = (wid & 3) * 16, wn = (wid >> 2) * 32;

    float cc[4][4];
#pragma unroll
    for (int j = 0; j < 4; j++)
#pragma unroll
        for (int q = 0; q < 4; q++) cc[j][q] = 0.f;

    auto compute = [&](int buf) {
        const char* sA = sbuf[buf];
        const char* sB = sbuf[buf] + OPBYTES;
        uint32_t ah[4], al[4];
        int ab = (wm + fr) * ARS + fc * 4;
        ah[0] = *(const uint32_t*)(sA + ab);
        ah[1] = *(const uint32_t*)(sA + ab + 8 * ARS);
        ah[2] = *(const uint32_t*)(sA + ab + 16);
        ah[3] = *(const uint32_t*)(sA + ab + 8 * ARS + 16);
        al[0] = *(const uint32_t*)(sA + LOFF + ab);
        al[1] = *(const uint32_t*)(sA + LOFF + ab + 8 * ARS);
        al[2] = *(const uint32_t*)(sA + LOFF + ab + 16);
        al[3] = *(const uint32_t*)(sA + LOFF + ab + 8 * ARS + 16);
#pragma unroll
        for (int j = 0; j < 4; j++) {
            int bb = (wn + j * 8 + fr) * ARS + fc * 4;
            uint32_t bh[2], bl[2];
            bh[0] = *(const uint32_t*)(sB + bb);
            bh[1] = *(const uint32_t*)(sB + bb + 16);
            bl[0] = *(const uint32_t*)(sB + LOFF + bb);
            bl[1] = *(const uint32_t*)(sB + LOFF + bb + 16);
            mma16816(cc[j], ah, bh);
            mma16816(cc[j], al, bh);
            mma16816(cc[j], ah, bl);
        }
    };

    const int NC = FD / 16;  // 128
    gload(0); gstore(0); gload(1);
    __syncthreads();
    for (int ci = 0; ci < NC; ci++) {
        compute(ci & 1);
        if (ci + 1 < NC) {
            gstore((ci + 1) & 1);
            if (ci + 2 < NC) gload(ci + 2);
            __syncthreads();
        }
    }

#pragma unroll
    for (int h = 0; h < 2; h++) {
        int row = wm + fr + h * 8;
        if (row < rows) {
            size_t rb = (size_t)(off + m0 + row) * HD + n0 + wn + fc * 2;
#pragma unroll
            for (int j = 0; j < 4; j++)
                *(float2*)(d_y + rb + j * 8) = make_float2(cc[j][h * 2 + 0], cc[j][h * 2 + 1]);
        }
    }
}

// ---------------- combine (proven R1) ----------------
__global__ __launch_bounds__(256) void combine_kernel(float* __restrict__ out)
{
    int t = blockIdx.x;
    int s0 = d_slot[t * 2 + 0], s1 = d_slot[t * 2 + 1];
    float w0 = d_tw[t * 2 + 0], w1 = d_tw[t * 2 + 1];
    const float* y0 = d_y + (size_t)s0 * HD;
    const float* y1 = d_y + (size_t)s1 * HD;
    float* o = out + (size_t)t * HD;
    for (int h = threadIdx.x * 4; h < HD; h += blockDim.x * 4) {
        float4 a = *(const float4*)(y0 + h);
        float4 b = *(const float4*)(y1 + h);
        *(float4*)(o + h) = make_float4(w0 * a.x + w1 * b.x, w0 * a.y + w1 * b.y,
                                        w0 * a.z + w1 * b.z, w0 * a.w + w1 * b.w);
    }
}

// ---------------- launch ----------------
extern "C" void kernel_launch(void* const* d_in, const int* in_sizes, int n_in,
                              void* d_out, int out_size)
{
    const float* x  = (const float*)d_in[0];
    const float* gw = (const float*)d_in[1];
    const float* Wg = (const float*)d_in[2];
    const float* Wu = (const float*)d_in[3];
    const float* Wd = (const float*)d_in[4];

    float* out = (float*)d_out;
    const int OUT_ELEMS = NT * HD;
    const int LOG_ELEMS = NT * NE;

    float* out_main = nullptr;
    float* out_logits = nullptr;
    if (out_size >= OUT_ELEMS + LOG_ELEMS) { out_main = out; out_logits = out + (size_t)OUT_ELEMS; }
    else if (out_size >= OUT_ELEMS)        { out_main = out; }
    else                                   { out_logits = out; }

    zero_counts_kernel<<<1, 32>>>();
    router_kernel<<<NT / 8, 256>>>(x, gw, out_logits);
    scan_kernel<<<1, 1>>>();
    remap_kernel<<<NE, 256>>>();

    if (out_main) {
        convert_x_kernel<<<(NT * HD / 4 + 255) / 256, 256>>>(x);
        dim3 tb(32, 8);
        transpose_split_kernel<<<dim3(FD / 32, HD / 32, NE), tb>>>(Wg, 0, HD, FD);
        transpose_split_kernel<<<dim3(FD / 32, HD / 32, NE), tb>>>(Wu, 1, HD, FD);
        transpose_split_kernel<<<dim3(HD / 32, FD / 32, NE), tb>>>(Wd, 2, FD, HD);

        gemm_gu_mma<<<dim3(FD / 64, NT / 64, NE), 256>>>();
        gemm_d_mma<<<dim3(HD / 64, NT / 64, NE), 256>>>();
        combine_kernel<<<NT, 256>>>(out_main);
    }
}

// round 13
// speedup vs baseline: 1.4595x; 1.4595x over previous
#include <cuda_runtime.h>
#include <cuda_bf16.h>
#include <cstdint>

#define NE 8
#define HD 1024
#define FD 2048
#define NT 8192
#define NSLOT (NT*2)

// ---------------- device scratch (R1/R6 proven) ----------------
__device__ int   d_count[NE];
__device__ int   d_offset[NE];
__device__ int   d_etok[NE * NT];
__device__ int   d_slot[NSLOT];
__device__ float d_tw[NSLOT];
__device__ float d_g[(size_t)NSLOT * FD];
__device__ float d_y[(size_t)NSLOT * HD];

// ---------------- helpers ----------------
__device__ __forceinline__ void mma16816(float* d, const uint32_t* a, const uint32_t* b) {
    asm volatile("mma.sync.aligned.m16n8k16.row.col.f32.bf16.bf16.f32 "
        "{%0,%1,%2,%3}, {%4,%5,%6,%7}, {%8,%9}, {%0,%1,%2,%3};"
        : "+f"(d[0]), "+f"(d[1]), "+f"(d[2]), "+f"(d[3])
        : "r"(a[0]), "r"(a[1]), "r"(a[2]), "r"(a[3]), "r"(b[0]), "r"(b[1]));
}
__device__ __forceinline__ uint32_t pack2(__nv_bfloat16 a, __nv_bfloat16 b) {
    return (uint32_t)__bfloat16_as_ushort(a) | ((uint32_t)__bfloat16_as_ushort(b) << 16);
}
__device__ __forceinline__ void split4(float4 v, uint2& hi, uint2& lo) {
    __nv_bfloat16 h0 = __float2bfloat16(v.x), h1 = __float2bfloat16(v.y);
    __nv_bfloat16 h2 = __float2bfloat16(v.z), h3 = __float2bfloat16(v.w);
    __nv_bfloat16 l0 = __float2bfloat16(v.x - __bfloat162float(h0));
    __nv_bfloat16 l1 = __float2bfloat16(v.y - __bfloat162float(h1));
    __nv_bfloat16 l2 = __float2bfloat16(v.z - __bfloat162float(h2));
    __nv_bfloat16 l3 = __float2bfloat16(v.w - __bfloat162float(h3));
    hi.x = pack2(h0, h1); hi.y = pack2(h2, h3);
    lo.x = pack2(l0, l1); lo.y = pack2(l2, l3);
}

#define ARS 40                 // bf16 tile row stride bytes (16k*2B + 8 pad)
#define ATILE (128 * ARS)      // 5120: A tile (128 rows), hi; lo follows
#define BTILE (64 * ARS)       // 2560: B tile (64 rows), hi; lo follows

// ---------------- routing (proven R1) ----------------
__global__ void zero_counts_kernel() {
    if (threadIdx.x < NE) d_count[threadIdx.x] = 0;
}
__global__ void scan_kernel() {
    int off = 0;
    for (int e = 0; e < NE; e++) { d_offset[e] = off; off += d_count[e]; }
}
__global__ void remap_kernel() {
    int e = blockIdx.x;
    int n = d_count[e], off = d_offset[e];
    for (int p = threadIdx.x; p < n; p += blockDim.x)
        d_slot[d_etok[e * NT + p]] = off + p;
}

__global__ __launch_bounds__(256) void router_kernel(
    const float* __restrict__ x, const float* __restrict__ gw,
    float* __restrict__ logits_out)
{
    __shared__ float gws[NE * HD];
    for (int i = threadIdx.x; i < NE * HD; i += blockDim.x) gws[i] = gw[i];
    __syncthreads();

    int warp = threadIdx.x >> 5, lane = threadIdx.x & 31;
    int t = blockIdx.x * 8 + warp;
    if (t >= NT) return;

    const float* xr = x + (size_t)t * HD;
    float acc[NE];
#pragma unroll
    for (int e = 0; e < NE; e++) acc[e] = 0.f;
    for (int h = lane * 4; h < HD; h += 128) {
        float4 xv = *(const float4*)(xr + h);
#pragma unroll
        for (int e = 0; e < NE; e++) {
            float4 wv = *(const float4*)(&gws[e * HD + h]);
            acc[e] += xv.x * wv.x + xv.y * wv.y + xv.z * wv.z + xv.w * wv.w;
        }
    }
#pragma unroll
    for (int e = 0; e < NE; e++)
        for (int o = 16; o > 0; o >>= 1)
            acc[e] += __shfl_xor_sync(0xffffffffu, acc[e], o);

    if (lane == 0) {
        if (logits_out) {
#pragma unroll
            for (int e = 0; e < NE; e++) logits_out[(size_t)t * NE + e] = acc[e];
        }
        float m = acc[0];
#pragma unroll
        for (int e = 1; e < NE; e++) m = fmaxf(m, acc[e]);
        float p[NE];
#pragma unroll
        for (int e = 0; e < NE; e++) p[e] = expf(acc[e] - m);
        int i1 = 0;
#pragma unroll
        for (int e = 1; e < NE; e++) if (p[e] > p[i1]) i1 = e;
        int i2 = (i1 == 0) ? 1 : 0;
#pragma unroll
        for (int e = 0; e < NE; e++) if (e != i1 && p[e] > p[i2]) i2 = e;
        float s2 = p[i1] + p[i2];
        d_tw[t * 2 + 0] = p[i1] / s2;
        d_tw[t * 2 + 1] = p[i2] / s2;
        int pos = atomicAdd(&d_count[i1], 1);
        d_etok[i1 * NT + pos] = t * 2 + 0;
        pos = atomicAdd(&d_count[i2], 1);
        d_etok[i2 * NT + pos] = t * 2 + 1;
    }
}

// ---------------- stage A: G = silu(X Wg)*(X Wu), mma.sync, CTA 128x64 ----------------
// 8 warps, warp tile m32 x n32 (i=0,1 A-fragment pairs). BK=16. Single buffer (R6 structure).
__global__ __launch_bounds__(256) void gemm_gu_mma(
    const float* __restrict__ x,
    const float* __restrict__ Wg, const float* __restrict__ Wu)
{
    __shared__ __align__(16) char sA[2 * ATILE];
    __shared__ __align__(16) char sBg[2 * BTILE];
    __shared__ __align__(16) char sBu[2 * BTILE];
    __shared__ int toks[128];

    int e = blockIdx.z;
    int n = d_count[e];
    int m0 = blockIdx.y * 128;
    if (m0 >= n) return;
    int off = d_offset[e];
    int n0 = blockIdx.x * 64;
    int rows = min(128, n - m0);

    int tid = threadIdx.x, lane = tid & 31, wid = tid >> 5;
    if (tid < 128) toks[tid] = d_etok[e * NT + m0 + min(tid, rows - 1)] >> 1;
    __syncthreads();

    const float* wg = Wg + (size_t)e * HD * FD;
    const float* wu = Wu + (size_t)e * HD * FD;

    int bn = tid & 63, bkq = tid >> 6;        // B: 64 n-rows x 4 k-quads
    int fr = lane >> 2, fc = lane & 3;
    int wm = (wid & 3) * 32, wn = (wid >> 2) * 32;

    float cg[2][4][4], cu[2][4][4];
#pragma unroll
    for (int i = 0; i < 2; i++)
#pragma unroll
        for (int j = 0; j < 4; j++)
#pragma unroll
            for (int q = 0; q < 4; q++) { cg[i][j][q] = 0.f; cu[i][j][q] = 0.f; }

    const int NC = HD / 16;  // 64
    for (int ci = 0; ci < NC; ci++) {
        int k0 = ci * 16;
        // ---- load + split + store (R6 pattern, A doubled) ----
        {
#pragma unroll
            for (int q = 0; q < 2; q++) {
                int idx = tid + q * 256;
                int r = idx >> 2, c = idx & 3;
                float4 av = *(const float4*)(x + (size_t)toks[r] * HD + k0 + c * 4);
                uint2 hi, lo; split4(av, hi, lo);
                *(uint2*)(sA + r * ARS + c * 8) = hi;
                *(uint2*)(sA + ATILE + r * ARS + c * 8) = lo;
            }
            int kb = k0 + bkq * 4;
            float4 gv, uv;
            gv.x = wg[(size_t)(kb + 0) * FD + n0 + bn];
            gv.y = wg[(size_t)(kb + 1) * FD + n0 + bn];
            gv.z = wg[(size_t)(kb + 2) * FD + n0 + bn];
            gv.w = wg[(size_t)(kb + 3) * FD + n0 + bn];
            uv.x = wu[(size_t)(kb + 0) * FD + n0 + bn];
            uv.y = wu[(size_t)(kb + 1) * FD + n0 + bn];
            uv.z = wu[(size_t)(kb + 2) * FD + n0 + bn];
            uv.w = wu[(size_t)(kb + 3) * FD + n0 + bn];
            uint2 hi, lo;
            split4(gv, hi, lo);
            *(uint2*)(sBg + bn * ARS + bkq * 8) = hi;
            *(uint2*)(sBg + BTILE + bn * ARS + bkq * 8) = lo;
            split4(uv, hi, lo);
            *(uint2*)(sBu + bn * ARS + bkq * 8) = hi;
            *(uint2*)(sBu + BTILE + bn * ARS + bkq * 8) = lo;
        }
        __syncthreads();
        // ---- fragments + mma ----
        {
            uint32_t ah[2][4], al[2][4];
#pragma unroll
            for (int i = 0; i < 2; i++) {
                int ab = (wm + i * 16 + fr) * ARS + fc * 4;
                ah[i][0] = *(const uint32_t*)(sA + ab);
                ah[i][1] = *(const uint32_t*)(sA + ab + 8 * ARS);
                ah[i][2] = *(const uint32_t*)(sA + ab + 16);
                ah[i][3] = *(const uint32_t*)(sA + ab + 8 * ARS + 16);
                al[i][0] = *(const uint32_t*)(sA + ATILE + ab);
                al[i][1] = *(const uint32_t*)(sA + ATILE + ab + 8 * ARS);
                al[i][2] = *(const uint32_t*)(sA + ATILE + ab + 16);
                al[i][3] = *(const uint32_t*)(sA + ATILE + ab + 8 * ARS + 16);
            }
#pragma unroll
            for (int j = 0; j < 4; j++) {
                int bb = (wn + j * 8 + fr) * ARS + fc * 4;
                uint32_t bh[2], bl[2];
                bh[0] = *(const uint32_t*)(sBg + bb);
                bh[1] = *(const uint32_t*)(sBg + bb + 16);
                bl[0] = *(const uint32_t*)(sBg + BTILE + bb);
                bl[1] = *(const uint32_t*)(sBg + BTILE + bb + 16);
#pragma unroll
                for (int i = 0; i < 2; i++) {
                    mma16816(cg[i][j], ah[i], bh);
                    mma16816(cg[i][j], al[i], bh);
                    mma16816(cg[i][j], ah[i], bl);
                }
                bh[0] = *(const uint32_t*)(sBu + bb);
                bh[1] = *(const uint32_t*)(sBu + bb + 16);
                bl[0] = *(const uint32_t*)(sBu + BTILE + bb);
                bl[1] = *(const uint32_t*)(sBu + BTILE + bb + 16);
#pragma unroll
                for (int i = 0; i < 2; i++) {
                    mma16816(cu[i][j], ah[i], bh);
                    mma16816(cu[i][j], al[i], bh);
                    mma16816(cu[i][j], ah[i], bl);
                }
            }
        }
        __syncthreads();
    }

    // ---- epilogue: silu(g)*u -> d_g fp32 ----
#pragma unroll
    for (int i = 0; i < 2; i++)
#pragma unroll
        for (int h = 0; h < 2; h++) {
            int row = wm + i * 16 + fr + h * 8;
            if (row < rows) {
                size_t rb = (size_t)(off + m0 + row) * FD + n0 + wn + fc * 2;
#pragma unroll
                for (int j = 0; j < 4; j++) {
                    float g0 = cg[i][j][h * 2 + 0], g1 = cg[i][j][h * 2 + 1];
                    float u0 = cu[i][j][h * 2 + 0], u1 = cu[i][j][h * 2 + 1];
                    float v0 = g0 / (1.f + expf(-g0)) * u0;
                    float v1 = g1 / (1.f + expf(-g1)) * u1;
                    *(float2*)(d_g + rb + j * 8) = make_float2(v0, v1);
                }
            }
        }
}

// ---------------- stage B: Y = G @ Wd, mma.sync, CTA 128x64 ----------------
__global__ __launch_bounds__(256) void gemm_d_mma(const float* __restrict__ Wd)
{
    __shared__ __align__(16) char sA[2 * ATILE];
    __shared__ __align__(16) char sB[2 * BTILE];

    int e = blockIdx.z;
    int n = d_count[e];
    int m0 = blockIdx.y * 128;
    if (m0 >= n) return;
    int off = d_offset[e];
    int n0 = blockIdx.x * 64;
    int rows = min(128, n - m0);

    int tid = threadIdx.x, lane = tid & 31, wid = tid >> 5;
    const float* wd = Wd + (size_t)e * FD * HD;

    int bn = tid & 63, bkq = tid >> 6;
    int fr = lane >> 2, fc = lane & 3;
    int wm = (wid & 3) * 32, wn = (wid >> 2) * 32;

    float cc[2][4][4];
#pragma unroll
    for (int i = 0; i < 2; i++)
#pragma unroll
        for (int j = 0; j < 4; j++)
#pragma unroll
            for (int q = 0; q < 4; q++) cc[i][j][q] = 0.f;

    const int NC = FD / 16;  // 128
    for (int ci = 0; ci < NC; ci++) {
        int k0 = ci * 16;
        {
#pragma unroll
            for (int q = 0; q < 2; q++) {
                int idx = tid + q * 256;
                int r = idx >> 2, c = idx & 3;
                int ar = min(r, rows - 1);
                float4 av = *(const float4*)(d_g + (size_t)(off + m0 + ar) * FD + k0 + c * 4);
                uint2 hi, lo; split4(av, hi, lo);
                *(uint2*)(sA + r * ARS + c * 8) = hi;
                *(uint2*)(sA + ATILE + r * ARS + c * 8) = lo;
            }
            int kb = k0 + bkq * 4;
            float4 bv;
            bv.x = wd[(size_t)(kb + 0) * HD + n0 + bn];
            bv.y = wd[(size_t)(kb + 1) * HD + n0 + bn];
            bv.z = wd[(size_t)(kb + 2) * HD + n0 + bn];
            bv.w = wd[(size_t)(kb + 3) * HD + n0 + bn];
            uint2 hi, lo; split4(bv, hi, lo);
            *(uint2*)(sB + bn * ARS + bkq * 8) = hi;
            *(uint2*)(sB + BTILE + bn * ARS + bkq * 8) = lo;
        }
        __syncthreads();
        {
            uint32_t ah[2][4], al[2][4];
#pragma unroll
            for (int i = 0; i < 2; i++) {
                int ab = (wm + i * 16 + fr) * ARS + fc * 4;
                ah[i][0] = *(const uint32_t*)(sA + ab);
                ah[i][1] = *(const uint32_t*)(sA + ab + 8 * ARS);
                ah[i][2] = *(const uint32_t*)(sA + ab + 16);
                ah[i][3] = *(const uint32_t*)(sA + ab + 8 * ARS + 16);
                al[i][0] = *(const uint32_t*)(sA + ATILE + ab);
                al[i][1] = *(const uint32_t*)(sA + ATILE + ab + 8 * ARS);
                al[i][2] = *(const uint32_t*)(sA + ATILE + ab + 16);
                al[i][3] = *(const uint32_t*)(sA + ATILE + ab + 8 * ARS + 16);
            }
#pragma unroll
            for (int j = 0; j < 4; j++) {
                int bb = (wn + j * 8 + fr) * ARS + fc * 4;
                uint32_t bh[2], bl[2];
                bh[0] = *(const uint32_t*)(sB + bb);
                bh[1] = *(const uint32_t*)(sB + bb + 16);
                bl[0] = *(const uint32_t*)(sB + BTILE + bb);
                bl[1] = *(const uint32_t*)(sB + BTILE + bb + 16);
#pragma unroll
                for (int i = 0; i < 2; i++) {
                    mma16816(cc[i][j], ah[i], bh);
                    mma16816(cc[i][j], al[i], bh);
                    mma16816(cc[i][j], ah[i], bl);
                }
            }
        }
        __syncthreads();
    }

#pragma unroll
    for (int i = 0; i < 2; i++)
#pragma unroll
        for (int h = 0; h < 2; h++) {
            int row = wm + i * 16 + fr + h * 8;
            if (row < rows) {
                size_t rb = (size_t)(off + m0 + row) * HD + n0 + wn + fc * 2;
#pragma unroll
                for (int j = 0; j < 4; j++)
                    *(float2*)(d_y + rb + j * 8) = make_float2(cc[i][j][h * 2 + 0], cc[i][j][h * 2 + 1]);
            }
        }
}

// ---------------- combine (proven R1) ----------------
__global__ __launch_bounds__(256) void combine_kernel(float* __restrict__ out)
{
    int t = blockIdx.x;
    int s0 = d_slot[t * 2 + 0], s1 = d_slot[t * 2 + 1];
    float w0 = d_tw[t * 2 + 0], w1 = d_tw[t * 2 + 1];
    const float* y0 = d_y + (size_t)s0 * HD;
    const float* y1 = d_y + (size_t)s1 * HD;
    float* o = out + (size_t)t * HD;
    for (int h = threadIdx.x * 4; h < HD; h += blockDim.x * 4) {
        float4 a = *(const float4*)(y0 + h);
        float4 b = *(const float4*)(y1 + h);
        *(float4*)(o + h) = make_float4(w0 * a.x + w1 * b.x, w0 * a.y + w1 * b.y,
                                        w0 * a.z + w1 * b.z, w0 * a.w + w1 * b.w);
    }
}

// ---------------- launch ----------------
extern "C" void kernel_launch(void* const* d_in, const int* in_sizes, int n_in,
                              void* d_out, int out_size)
{
    const float* x  = (const float*)d_in[0];
    const float* gw = (const float*)d_in[1];
    const float* Wg = (const float*)d_in[2];
    const float* Wu = (const float*)d_in[3];
    const float* Wd = (const float*)d_in[4];

    float* out = (float*)d_out;
    const int OUT_ELEMS = NT * HD;
    const int LOG_ELEMS = NT * NE;

    float* out_main = nullptr;
    float* out_logits = nullptr;
    if (out_size >= OUT_ELEMS + LOG_ELEMS) { out_main = out; out_logits = out + (size_t)OUT_ELEMS; }
    else if (out_size >= OUT_ELEMS)        { out_main = out; }
    else                                   { out_logits = out; }

    zero_counts_kernel<<<1, 32>>>();
    router_kernel<<<NT / 8, 256>>>(x, gw, out_logits);
    scan_kernel<<<1, 1>>>();
    remap_kernel<<<NE, 256>>>();

    if (out_main) {
        gemm_gu_mma<<<dim3(FD / 64, NT / 128, NE), 256>>>(x, Wg, Wu);
        gemm_d_mma<<<dim3(HD / 64, NT / 128, NE), 256>>>(Wd);
        combine_kernel<<<NT, 256>>>(out_main);
    }
}

// round 15
// speedup vs baseline: 1.7045x; 1.1678x over previous
#include <cuda_runtime.h>
#include <cuda_bf16.h>
#include <cstdint>

#define NE 8
#define HD 1024
#define FD 2048
#define NT 8192
#define NSLOT (NT*2)

// ---------------- device scratch (R1/R6 proven) ----------------
__device__ int   d_count[NE];
__device__ int   d_offset[NE];
__device__ int   d_etok[NE * NT];
__device__ int   d_slot[NSLOT];
__device__ float d_tw[NSLOT];
__device__ float d_g[(size_t)NSLOT * FD];
__device__ float d_y[(size_t)NSLOT * HD];

// ---------------- helpers ----------------
__device__ __forceinline__ void mma16816(float* d, const uint32_t* a, const uint32_t* b) {
    asm volatile("mma.sync.aligned.m16n8k16.row.col.f32.bf16.bf16.f32 "
        "{%0,%1,%2,%3}, {%4,%5,%6,%7}, {%8,%9}, {%0,%1,%2,%3};"
        : "+f"(d[0]), "+f"(d[1]), "+f"(d[2]), "+f"(d[3])
        : "r"(a[0]), "r"(a[1]), "r"(a[2]), "r"(a[3]), "r"(b[0]), "r"(b[1]));
}
__device__ __forceinline__ uint32_t pack2(__nv_bfloat16 a, __nv_bfloat16 b) {
    return (uint32_t)__bfloat16_as_ushort(a) | ((uint32_t)__bfloat16_as_ushort(b) << 16);
}
__device__ __forceinline__ void split4(float4 v, uint2& hi, uint2& lo) {
    __nv_bfloat16 h0 = __float2bfloat16(v.x), h1 = __float2bfloat16(v.y);
    __nv_bfloat16 h2 = __float2bfloat16(v.z), h3 = __float2bfloat16(v.w);
    __nv_bfloat16 l0 = __float2bfloat16(v.x - __bfloat162float(h0));
    __nv_bfloat16 l1 = __float2bfloat16(v.y - __bfloat162float(h1));
    __nv_bfloat16 l2 = __float2bfloat16(v.z - __bfloat162float(h2));
    __nv_bfloat16 l3 = __float2bfloat16(v.w - __bfloat162float(h3));
    hi.x = pack2(h0, h1); hi.y = pack2(h2, h3);
    lo.x = pack2(l0, l1); lo.y = pack2(l2, l3);
}

#define ARS 40                 // bf16 tile row stride bytes (16k*2B + 8 pad)
#define ATILE (128 * ARS)      // 5120: A tile (128 rows), hi; lo follows
#define BTILE (64 * ARS)       // 2560: B tile (64 rows), hi; lo follows

// ---------------- routing (proven R1) ----------------
__global__ void zero_counts_kernel() {
    if (threadIdx.x < NE) d_count[threadIdx.x] = 0;
}
__global__ void scan_kernel() {
    int off = 0;
    for (int e = 0; e < NE; e++) { d_offset[e] = off; off += d_count[e]; }
}
__global__ void remap_kernel() {
    int e = blockIdx.x;
    int n = d_count[e], off = d_offset[e];
    for (int p = threadIdx.x; p < n; p += blockDim.x)
        d_slot[d_etok[e * NT + p]] = off + p;
}

__global__ __launch_bounds__(256) void router_kernel(
    const float* __restrict__ x, const float* __restrict__ gw,
    float* __restrict__ logits_out)
{
    __shared__ float gws[NE * HD];
    for (int i = threadIdx.x; i < NE * HD; i += blockDim.x) gws[i] = gw[i];
    __syncthreads();

    int warp = threadIdx.x >> 5, lane = threadIdx.x & 31;
    int t = blockIdx.x * 8 + warp;
    if (t >= NT) return;

    const float* xr = x + (size_t)t * HD;
    float acc[NE];
#pragma unroll
    for (int e = 0; e < NE; e++) acc[e] = 0.f;
    for (int h = lane * 4; h < HD; h += 128) {
        float4 xv = *(const float4*)(xr + h);
#pragma unroll
        for (int e = 0; e < NE; e++) {
            float4 wv = *(const float4*)(&gws[e * HD + h]);
            acc[e] += xv.x * wv.x + xv.y * wv.y + xv.z * wv.z + xv.w * wv.w;
        }
    }
#pragma unroll
    for (int e = 0; e < NE; e++)
        for (int o = 16; o > 0; o >>= 1)
            acc[e] += __shfl_xor_sync(0xffffffffu, acc[e], o);

    if (lane == 0) {
        if (logits_out) {
#pragma unroll
            for (int e = 0; e < NE; e++) logits_out[(size_t)t * NE + e] = acc[e];
        }
        float m = acc[0];
#pragma unroll
        for (int e = 1; e < NE; e++) m = fmaxf(m, acc[e]);
        float p[NE];
#pragma unroll
        for (int e = 0; e < NE; e++) p[e] = expf(acc[e] - m);
        int i1 = 0;
#pragma unroll
        for (int e = 1; e < NE; e++) if (p[e] > p[i1]) i1 = e;
        int i2 = (i1 == 0) ? 1 : 0;
#pragma unroll
        for (int e = 0; e < NE; e++) if (e != i1 && p[e] > p[i2]) i2 = e;
        float s2 = p[i1] + p[i2];
        d_tw[t * 2 + 0] = p[i1] / s2;
        d_tw[t * 2 + 1] = p[i2] / s2;
        int pos = atomicAdd(&d_count[i1], 1);
        d_etok[i1 * NT + pos] = t * 2 + 0;
        pos = atomicAdd(&d_count[i2], 1);
        d_etok[i2 * NT + pos] = t * 2 + 1;
    }
}

// ---------------- stage A: G = silu(X Wg)*(X Wu), CTA 128x64, double-buffered ----------------
// 8 warps, warp tile m32 x n32. BK=16. Register prefetch + one sync per chunk.
__global__ __launch_bounds__(256) void gemm_gu_mma(
    const float* __restrict__ x,
    const float* __restrict__ Wg, const float* __restrict__ Wu)
{
    __shared__ __align__(16) char sA[2][2 * ATILE];
    __shared__ __align__(16) char sBg[2][2 * BTILE];
    __shared__ __align__(16) char sBu[2][2 * BTILE];
    __shared__ int toks[128];

    int e = blockIdx.z;
    int n = d_count[e];
    int m0 = blockIdx.y * 128;
    if (m0 >= n) return;
    int off = d_offset[e];
    int n0 = blockIdx.x * 64;
    int rows = min(128, n - m0);

    int tid = threadIdx.x, lane = tid & 31, wid = tid >> 5;
    if (tid < 128) toks[tid] = d_etok[e * NT + m0 + min(tid, rows - 1)] >> 1;
    __syncthreads();

    const float* wg = Wg + (size_t)e * HD * FD;
    const float* wu = Wu + (size_t)e * HD * FD;

    int bn = tid & 63, bkq = tid >> 6;        // B: 64 n-rows x 4 k-quads
    int fr = lane >> 2, fc = lane & 3;
    int wm = (wid & 3) * 32, wn = (wid >> 2) * 32;

    // per-thread A-load coords
    int ar0 = tid >> 2, ac0 = tid & 3;        // idx = tid
    int ar1 = (tid + 256) >> 2, ac1 = tid & 3; // idx = tid+256 (c identical)

    float4 rav[2], rgv, ruv;
    auto gload = [&](int ci) {
        int k0 = ci * 16;
        rav[0] = *(const float4*)(x + (size_t)toks[ar0] * HD + k0 + ac0 * 4);
        rav[1] = *(const float4*)(x + (size_t)toks[ar1] * HD + k0 + ac1 * 4);
        int kb = k0 + bkq * 4;
        rgv.x = wg[(size_t)(kb + 0) * FD + n0 + bn];
        rgv.y = wg[(size_t)(kb + 1) * FD + n0 + bn];
        rgv.z = wg[(size_t)(kb + 2) * FD + n0 + bn];
        rgv.w = wg[(size_t)(kb + 3) * FD + n0 + bn];
        ruv.x = wu[(size_t)(kb + 0) * FD + n0 + bn];
        ruv.y = wu[(size_t)(kb + 1) * FD + n0 + bn];
        ruv.z = wu[(size_t)(kb + 2) * FD + n0 + bn];
        ruv.w = wu[(size_t)(kb + 3) * FD + n0 + bn];
    };
    auto gstore = [&](int buf) {
        uint2 hi, lo;
        split4(rav[0], hi, lo);
        *(uint2*)(sA[buf] + ar0 * ARS + ac0 * 8) = hi;
        *(uint2*)(sA[buf] + ATILE + ar0 * ARS + ac0 * 8) = lo;
        split4(rav[1], hi, lo);
        *(uint2*)(sA[buf] + ar1 * ARS + ac1 * 8) = hi;
        *(uint2*)(sA[buf] + ATILE + ar1 * ARS + ac1 * 8) = lo;
        split4(rgv, hi, lo);
        *(uint2*)(sBg[buf] + bn * ARS + bkq * 8) = hi;
        *(uint2*)(sBg[buf] + BTILE + bn * ARS + bkq * 8) = lo;
        split4(ruv, hi, lo);
        *(uint2*)(sBu[buf] + bn * ARS + bkq * 8) = hi;
        *(uint2*)(sBu[buf] + BTILE + bn * ARS + bkq * 8) = lo;
    };

    float cg[2][4][4], cu[2][4][4];
#pragma unroll
    for (int i = 0; i < 2; i++)
#pragma unroll
        for (int j = 0; j < 4; j++)
#pragma unroll
            for (int q = 0; q < 4; q++) { cg[i][j][q] = 0.f; cu[i][j][q] = 0.f; }

    auto compute = [&](int buf) {
        const char* pA = sA[buf];
        const char* pBg = sBg[buf];
        const char* pBu = sBu[buf];
        uint32_t ah[2][4], al[2][4];
#pragma unroll
        for (int i = 0; i < 2; i++) {
            int ab = (wm + i * 16 + fr) * ARS + fc * 4;
            ah[i][0] = *(const uint32_t*)(pA + ab);
            ah[i][1] = *(const uint32_t*)(pA + ab + 8 * ARS);
            ah[i][2] = *(const uint32_t*)(pA + ab + 16);
            ah[i][3] = *(const uint32_t*)(pA + ab + 8 * ARS + 16);
            al[i][0] = *(const uint32_t*)(pA + ATILE + ab);
            al[i][1] = *(const uint32_t*)(pA + ATILE + ab + 8 * ARS);
            al[i][2] = *(const uint32_t*)(pA + ATILE + ab + 16);
            al[i][3] = *(const uint32_t*)(pA + ATILE + ab + 8 * ARS + 16);
        }
#pragma unroll
        for (int j = 0; j < 4; j++) {
            int bb = (wn + j * 8 + fr) * ARS + fc * 4;
            uint32_t bh[2], bl[2];
            bh[0] = *(const uint32_t*)(pBg + bb);
            bh[1] = *(const uint32_t*)(pBg + bb + 16);
            bl[0] = *(const uint32_t*)(pBg + BTILE + bb);
            bl[1] = *(const uint32_t*)(pBg + BTILE + bb + 16);
#pragma unroll
            for (int i = 0; i < 2; i++) {
                mma16816(cg[i][j], ah[i], bh);
                mma16816(cg[i][j], al[i], bh);
                mma16816(cg[i][j], ah[i], bl);
            }
            bh[0] = *(const uint32_t*)(pBu + bb);
            bh[1] = *(const uint32_t*)(pBu + bb + 16);
            bl[0] = *(const uint32_t*)(pBu + BTILE + bb);
            bl[1] = *(const uint32_t*)(pBu + BTILE + bb + 16);
#pragma unroll
            for (int i = 0; i < 2; i++) {
                mma16816(cu[i][j], ah[i], bh);
                mma16816(cu[i][j], al[i], bh);
                mma16816(cu[i][j], ah[i], bl);
            }
        }
    };

    const int NC = HD / 16;  // 64
    gload(0); gstore(0);
    __syncthreads();
    for (int ci = 0; ci < NC; ci++) {
        if (ci + 1 < NC) gload(ci + 1);   // overlap with compute below
        compute(ci & 1);
        if (ci + 1 < NC) {
            gstore((ci + 1) & 1);
            __syncthreads();
        }
    }

    // ---- epilogue: silu(g)*u -> d_g fp32 ----
#pragma unroll
    for (int i = 0; i < 2; i++)
#pragma unroll
        for (int h = 0; h < 2; h++) {
            int row = wm + i * 16 + fr + h * 8;
            if (row < rows) {
                size_t rb = (size_t)(off + m0 + row) * FD + n0 + wn + fc * 2;
#pragma unroll
                for (int j = 0; j < 4; j++) {
                    float g0 = cg[i][j][h * 2 + 0], g1 = cg[i][j][h * 2 + 1];
                    float u0 = cu[i][j][h * 2 + 0], u1 = cu[i][j][h * 2 + 1];
                    float v0 = g0 / (1.f + expf(-g0)) * u0;
                    float v1 = g1 / (1.f + expf(-g1)) * u1;
                    *(float2*)(d_g + rb + j * 8) = make_float2(v0, v1);
                }
            }
        }
}

// ---------------- stage B: Y = G @ Wd, CTA 128x64, double-buffered ----------------
__global__ __launch_bounds__(256) void gemm_d_mma(const float* __restrict__ Wd)
{
    __shared__ __align__(16) char sA[2][2 * ATILE];
    __shared__ __align__(16) char sB[2][2 * BTILE];

    int e = blockIdx.z;
    int n = d_count[e];
    int m0 = blockIdx.y * 128;
    if (m0 >= n) return;
    int off = d_offset[e];
    int n0 = blockIdx.x * 64;
    int rows = min(128, n - m0);

    int tid = threadIdx.x, lane = tid & 31, wid = tid >> 5;
    const float* wd = Wd + (size_t)e * FD * HD;

    int bn = tid & 63, bkq = tid >> 6;
    int fr = lane >> 2, fc = lane & 3;
    int wm = (wid & 3) * 32, wn = (wid >> 2) * 32;

    int ar0 = tid >> 2, ac0 = tid & 3;
    int ar1 = (tid + 256) >> 2, ac1 = tid & 3;
    int am0 = min(ar0, rows - 1), am1 = min(ar1, rows - 1);
    const float* as0 = d_g + (size_t)(off + m0 + am0) * FD + ac0 * 4;
    const float* as1 = d_g + (size_t)(off + m0 + am1) * FD + ac1 * 4;

    float4 rav[2], rbv;
    auto gload = [&](int ci) {
        int k0 = ci * 16;
        rav[0] = *(const float4*)(as0 + k0);
        rav[1] = *(const float4*)(as1 + k0);
        int kb = k0 + bkq * 4;
        rbv.x = wd[(size_t)(kb + 0) * HD + n0 + bn];
        rbv.y = wd[(size_t)(kb + 1) * HD + n0 + bn];
        rbv.z = wd[(size_t)(kb + 2) * HD + n0 + bn];
        rbv.w = wd[(size_t)(kb + 3) * HD + n0 + bn];
    };
    auto gstore = [&](int buf) {
        uint2 hi, lo;
        split4(rav[0], hi, lo);
        *(uint2*)(sA[buf] + ar0 * ARS + ac0 * 8) = hi;
        *(uint2*)(sA[buf] + ATILE + ar0 * ARS + ac0 * 8) = lo;
        split4(rav[1], hi, lo);
        *(uint2*)(sA[buf] + ar1 * ARS + ac1 * 8) = hi;
        *(uint2*)(sA[buf] + ATILE + ar1 * ARS + ac1 * 8) = lo;
        split4(rbv, hi, lo);
        *(uint2*)(sB[buf] + bn * ARS + bkq * 8) = hi;
        *(uint2*)(sB[buf] + BTILE + bn * ARS + bkq * 8) = lo;
    };

    float cc[2][4][4];
#pragma unroll
    for (int i = 0; i < 2; i++)
#pragma unroll
        for (int j = 0; j < 4; j++)
#pragma unroll
            for (int q = 0; q < 4; q++) cc[i][j][q] = 0.f;

    auto compute = [&](int buf) {
        const char* pA = sA[buf];
        const char* pB = sB[buf];
        uint32_t ah[2][4], al[2][4];
#pragma unroll
        for (int i = 0; i < 2; i++) {
            int ab = (wm + i * 16 + fr) * ARS + fc * 4;
            ah[i][0] = *(const uint32_t*)(pA + ab);
            ah[i][1] = *(const uint32_t*)(pA + ab + 8 * ARS);
            ah[i][2] = *(const uint32_t*)(pA + ab + 16);
            ah[i][3] = *(const uint32_t*)(pA + ab + 8 * ARS + 16);
            al[i][0] = *(const uint32_t*)(pA + ATILE + ab);
            al[i][1] = *(const uint32_t*)(pA + ATILE + ab + 8 * ARS);
            al[i][2] = *(const uint32_t*)(pA + ATILE + ab + 16);
            al[i][3] = *(const uint32_t*)(pA + ATILE + ab + 8 * ARS + 16);
        }
#pragma unroll
        for (int j = 0; j < 4; j++) {
            int bb = (wn + j * 8 + fr) * ARS + fc * 4;
            uint32_t bh[2], bl[2];
            bh[0] = *(const uint32_t*)(pB + bb);
            bh[1] = *(const uint32_t*)(pB + bb + 16);
            bl[0] = *(const uint32_t*)(pB + BTILE + bb);
            bl[1] = *(const uint32_t*)(pB + BTILE + bb + 16);
#pragma unroll
            for (int i = 0; i < 2; i++) {
                mma16816(cc[i][j], ah[i], bh);
                mma16816(cc[i][j], al[i], bh);
                mma16816(cc[i][j], ah[i], bl);
            }
        }
    };

    const int NC = FD / 16;  // 128
    gload(0); gstore(0);
    __syncthreads();
    for (int ci = 0; ci < NC; ci++) {
        if (ci + 1 < NC) gload(ci + 1);
        compute(ci & 1);
        if (ci + 1 < NC) {
            gstore((ci + 1) & 1);
            __syncthreads();
        }
    }

#pragma unroll
    for (int i = 0; i < 2; i++)
#pragma unroll
        for (int h = 0; h < 2; h++) {
            int row = wm + i * 16 + fr + h * 8;
            if (row < rows) {
                size_t rb = (size_t)(off + m0 + row) * HD + n0 + wn + fc * 2;
#pragma unroll
                for (int j = 0; j < 4; j++)
                    *(float2*)(d_y + rb + j * 8) = make_float2(cc[i][j][h * 2 + 0], cc[i][j][h * 2 + 1]);
            }
        }
}

// ---------------- combine (proven R1) ----------------
__global__ __launch_bounds__(256) void combine_kernel(float* __restrict__ out)
{
    int t = blockIdx.x;
    int s0 = d_slot[t * 2 + 0], s1 = d_slot[t * 2 + 1];
    float w0 = d_tw[t * 2 + 0], w1 = d_tw[t * 2 + 1];
    const float* y0 = d_y + (size_t)s0 * HD;
    const float* y1 = d_y + (size_t)s1 * HD;
    float* o = out + (size_t)t * HD;
    for (int h = threadIdx.x * 4; h < HD; h += blockDim.x * 4) {
        float4 a = *(const float4*)(y0 + h);
        float4 b = *(const float4*)(y1 + h);
        *(float4*)(o + h) = make_float4(w0 * a.x + w1 * b.x, w0 * a.y + w1 * b.y,
                                        w0 * a.z + w1 * b.z, w0 * a.w + w1 * b.w);
    }
}

// ---------------- launch ----------------
extern "C" void kernel_launch(void* const* d_in, const int* in_sizes, int n_in,
                              void* d_out, int out_size)
{
    const float* x  = (const float*)d_in[0];
    const float* gw = (const float*)d_in[1];
    const float* Wg = (const float*)d_in[2];
    const float* Wu = (const float*)d_in[3];
    const float* Wd = (const float*)d_in[4];

    float* out = (float*)d_out;
    const int OUT_ELEMS = NT * HD;
    const int LOG_ELEMS = NT * NE;

    float* out_main = nullptr;
    float* out_logits = nullptr;
    if (out_size >= OUT_ELEMS + LOG_ELEMS) { out_main = out; out_logits = out + (size_t)OUT_ELEMS; }
    else if (out_size >= OUT_ELEMS)        { out_main = out; }
    else                                   { out_logits = out; }

    zero_counts_kernel<<<1, 32>>>();
    router_kernel<<<NT / 8, 256>>>(x, gw, out_logits);
    scan_kernel<<<1, 1>>>();
    remap_kernel<<<NE, 256>>>();

    if (out_main) {
        gemm_gu_mma<<<dim3(FD / 64, NT / 128, NE), 256>>>(x, Wg, Wu);
        gemm_d_mma<<<dim3(HD / 64, NT / 128, NE), 256>>>(Wd);
        combine_kernel<<<NT, 256>>>(out_main);
    }
}

// round 16
// speedup vs baseline: 1.8425x; 1.0810x over previous
#include <cuda_runtime.h>
#include <cuda_bf16.h>
#include <cstdint>

#define NE 8
#define HD 1024
#define FD 2048
#define NT 8192
#define NSLOT (NT*2)

// ---------------- device scratch (R1/R6 proven) ----------------
__device__ int   d_count[NE];
__device__ int   d_offset[NE];
__device__ int   d_etok[NE * NT];
__device__ int   d_slot[NSLOT];
__device__ float d_tw[NSLOT];
__device__ float d_g[(size_t)NSLOT * FD];
__device__ float d_y[(size_t)NSLOT * HD];

// ---------------- helpers ----------------
__device__ __forceinline__ uint32_t smem_u32(const void* p) {
    uint32_t a;
    asm("{ .reg .u64 t; cvta.to.shared.u64 t, %1; cvt.u32.u64 %0, t; }" : "=r"(a) : "l"(p));
    return a;
}
__device__ __forceinline__ void ldsm4(uint32_t* r, uint32_t addr) {
    asm volatile("ldmatrix.sync.aligned.m8n8.x4.shared.b16 {%0,%1,%2,%3}, [%4];"
        : "=r"(r[0]), "=r"(r[1]), "=r"(r[2]), "=r"(r[3]) : "r"(addr));
}
__device__ __forceinline__ void mma16816(float* d, const uint32_t* a, const uint32_t* b) {
    asm volatile("mma.sync.aligned.m16n8k16.row.col.f32.bf16.bf16.f32 "
        "{%0,%1,%2,%3}, {%4,%5,%6,%7}, {%8,%9}, {%0,%1,%2,%3};"
        : "+f"(d[0]), "+f"(d[1]), "+f"(d[2]), "+f"(d[3])
        : "r"(a[0]), "r"(a[1]), "r"(a[2]), "r"(a[3]), "r"(b[0]), "r"(b[1]));
}
__device__ __forceinline__ uint32_t pack2(__nv_bfloat16 a, __nv_bfloat16 b) {
    return (uint32_t)__bfloat16_as_ushort(a) | ((uint32_t)__bfloat16_as_ushort(b) << 16);
}
__device__ __forceinline__ void split4(float4 v, uint2& hi, uint2& lo) {
    __nv_bfloat16 h0 = __float2bfloat16(v.x), h1 = __float2bfloat16(v.y);
    __nv_bfloat16 h2 = __float2bfloat16(v.z), h3 = __float2bfloat16(v.w);
    __nv_bfloat16 l0 = __float2bfloat16(v.x - __bfloat162float(h0));
    __nv_bfloat16 l1 = __float2bfloat16(v.y - __bfloat162float(h1));
    __nv_bfloat16 l2 = __float2bfloat16(v.z - __bfloat162float(h2));
    __nv_bfloat16 l3 = __float2bfloat16(v.w - __bfloat162float(h3));
    hi.x = pack2(h0, h1); hi.y = pack2(h2, h3);
    lo.x = pack2(l0, l1); lo.y = pack2(l2, l3);
}

// 64B rows: chunks [hi k0-7 | hi k8-15 | lo k0-7 | lo k8-15], chunk XOR-swizzled by (row>>1)&3.
// Conflict-free for ldmatrix (even rows cover banks 0-15 via 4 distinct chunks, odd rows 16-31).
__device__ __forceinline__ uint32_t swz(int row, int chunk) {
    return (uint32_t)(row * 64 + ((chunk ^ ((row >> 1) & 3)) * 16));
}
#define ATILE (128 * 64)   // 8192
#define BTILE (64 * 64)    // 4096

// ---------------- routing (proven R1) ----------------
__global__ void zero_counts_kernel() {
    if (threadIdx.x < NE) d_count[threadIdx.x] = 0;
}
__global__ void scan_kernel() {
    int off = 0;
    for (int e = 0; e < NE; e++) { d_offset[e] = off; off += d_count[e]; }
}
__global__ void remap_kernel() {
    int e = blockIdx.x;
    int n = d_count[e], off = d_offset[e];
    for (int p = threadIdx.x; p < n; p += blockDim.x)
        d_slot[d_etok[e * NT + p]] = off + p;
}

__global__ __launch_bounds__(256) void router_kernel(
    const float* __restrict__ x, const float* __restrict__ gw,
    float* __restrict__ logits_out)
{
    __shared__ float gws[NE * HD];
    for (int i = threadIdx.x; i < NE * HD; i += blockDim.x) gws[i] = gw[i];
    __syncthreads();

    int warp = threadIdx.x >> 5, lane = threadIdx.x & 31;
    int t = blockIdx.x * 8 + warp;
    if (t >= NT) return;

    const float* xr = x + (size_t)t * HD;
    float acc[NE];
#pragma unroll
    for (int e = 0; e < NE; e++) acc[e] = 0.f;
    for (int h = lane * 4; h < HD; h += 128) {
        float4 xv = *(const float4*)(xr + h);
#pragma unroll
        for (int e = 0; e < NE; e++) {
            float4 wv = *(const float4*)(&gws[e * HD + h]);
            acc[e] += xv.x * wv.x + xv.y * wv.y + xv.z * wv.z + xv.w * wv.w;
        }
    }
#pragma unroll
    for (int e = 0; e < NE; e++)
        for (int o = 16; o > 0; o >>= 1)
            acc[e] += __shfl_xor_sync(0xffffffffu, acc[e], o);

    if (lane == 0) {
        if (logits_out) {
#pragma unroll
            for (int e = 0; e < NE; e++) logits_out[(size_t)t * NE + e] = acc[e];
        }
        float m = acc[0];
#pragma unroll
        for (int e = 1; e < NE; e++) m = fmaxf(m, acc[e]);
        float p[NE];
#pragma unroll
        for (int e = 0; e < NE; e++) p[e] = expf(acc[e] - m);
        int i1 = 0;
#pragma unroll
        for (int e = 1; e < NE; e++) if (p[e] > p[i1]) i1 = e;
        int i2 = (i1 == 0) ? 1 : 0;
#pragma unroll
        for (int e = 0; e < NE; e++) if (e != i1 && p[e] > p[i2]) i2 = e;
        float s2 = p[i1] + p[i2];
        d_tw[t * 2 + 0] = p[i1] / s2;
        d_tw[t * 2 + 1] = p[i2] / s2;
        int pos = atomicAdd(&d_count[i1], 1);
        d_etok[i1 * NT + pos] = t * 2 + 0;
        pos = atomicAdd(&d_count[i2], 1);
        d_etok[i2 * NT + pos] = t * 2 + 1;
    }
}

// ---------------- stage A: G = silu(X Wg)*(X Wu), CTA 128x64, double-buffered, ldmatrix ----------------
__global__ __launch_bounds__(256) void gemm_gu_mma(
    const float* __restrict__ x,
    const float* __restrict__ Wg, const float* __restrict__ Wu)
{
    __shared__ __align__(16) char sA[2][ATILE];
    __shared__ __align__(16) char sBg[2][BTILE];
    __shared__ __align__(16) char sBu[2][BTILE];
    __shared__ int toks[128];

    int e = blockIdx.z;
    int n = d_count[e];
    int m0 = blockIdx.y * 128;
    if (m0 >= n) return;
    int off = d_offset[e];
    int n0 = blockIdx.x * 64;
    int rows = min(128, n - m0);

    int tid = threadIdx.x, lane = tid & 31, wid = tid >> 5;
    if (tid < 128) toks[tid] = d_etok[e * NT + m0 + min(tid, rows - 1)] >> 1;
    __syncthreads();

    const float* wg = Wg + (size_t)e * HD * FD;
    const float* wu = Wu + (size_t)e * HD * FD;

    int bn = tid & 63, bkq = tid >> 6;        // B: 64 n-rows x 4 k-quads
    int wm = (wid & 3) * 32, wn = (wid >> 2) * 32;

    // per-thread A-load coords (two batches)
    int ar0 = tid >> 2, ac0 = tid & 3;
    int ar1 = ar0 + 64, ac1 = ac0;

    // store offsets (swizzled)
    uint32_t sth0 = swz(ar0, ac0 >> 1) + (ac0 & 1) * 8;
    uint32_t stl0 = swz(ar0, 2 + (ac0 >> 1)) + (ac0 & 1) * 8;
    uint32_t sth1 = swz(ar1, ac1 >> 1) + (ac1 & 1) * 8;
    uint32_t stl1 = swz(ar1, 2 + (ac1 >> 1)) + (ac1 & 1) * 8;
    uint32_t bsth = swz(bn, bkq >> 1) + (bkq & 1) * 8;
    uint32_t bstl = swz(bn, 2 + (bkq >> 1)) + (bkq & 1) * 8;

    // ldmatrix per-thread addresses
    int lr = lane & 15, lc = lane >> 4;
    uint32_t aoh[2], aol[2], boh[2], bol[2];
#pragma unroll
    for (int i = 0; i < 2; i++) {
        int r = wm + i * 16 + lr;
        aoh[i] = swz(r, lc);
        aol[i] = swz(r, 2 + lc);
    }
#pragma unroll
    for (int jj = 0; jj < 2; jj++) {
        int r = wn + jj * 16 + lr;
        boh[jj] = swz(r, lc);
        bol[jj] = swz(r, 2 + lc);
    }

    float4 rav[2], rgv, ruv;
    auto gload = [&](int ci) {
        int k0 = ci * 16;
        rav[0] = *(const float4*)(x + (size_t)toks[ar0] * HD + k0 + ac0 * 4);
        rav[1] = *(const float4*)(x + (size_t)toks[ar1] * HD + k0 + ac1 * 4);
        int kb = k0 + bkq * 4;
        rgv.x = wg[(size_t)(kb + 0) * FD + n0 + bn];
        rgv.y = wg[(size_t)(kb + 1) * FD + n0 + bn];
        rgv.z = wg[(size_t)(kb + 2) * FD + n0 + bn];
        rgv.w = wg[(size_t)(kb + 3) * FD + n0 + bn];
        ruv.x = wu[(size_t)(kb + 0) * FD + n0 + bn];
        ruv.y = wu[(size_t)(kb + 1) * FD + n0 + bn];
        ruv.z = wu[(size_t)(kb + 2) * FD + n0 + bn];
        ruv.w = wu[(size_t)(kb + 3) * FD + n0 + bn];
    };
    auto gstore = [&](int buf) {
        uint2 hi, lo;
        split4(rav[0], hi, lo);
        *(uint2*)(sA[buf] + sth0) = hi;
        *(uint2*)(sA[buf] + stl0) = lo;
        split4(rav[1], hi, lo);
        *(uint2*)(sA[buf] + sth1) = hi;
        *(uint2*)(sA[buf] + stl1) = lo;
        split4(rgv, hi, lo);
        *(uint2*)(sBg[buf] + bsth) = hi;
        *(uint2*)(sBg[buf] + bstl) = lo;
        split4(ruv, hi, lo);
        *(uint2*)(sBu[buf] + bsth) = hi;
        *(uint2*)(sBu[buf] + bstl) = lo;
    };

    float cg[2][4][4], cu[2][4][4];
#pragma unroll
    for (int i = 0; i < 2; i++)
#pragma unroll
        for (int j = 0; j < 4; j++)
#pragma unroll
            for (int q = 0; q < 4; q++) { cg[i][j][q] = 0.f; cu[i][j][q] = 0.f; }

    auto compute = [&](int buf) {
        uint32_t uA = smem_u32(sA[buf]);
        uint32_t uBg = smem_u32(sBg[buf]);
        uint32_t uBu = smem_u32(sBu[buf]);
        uint32_t ah[2][4], al[2][4];
        ldsm4(ah[0], uA + aoh[0]);
        ldsm4(ah[1], uA + aoh[1]);
        ldsm4(al[0], uA + aol[0]);
        ldsm4(al[1], uA + aol[1]);
        uint32_t B0[4], B1[4];
        // gate hi: terms ah*bh, al*bh
        ldsm4(B0, uBg + boh[0]);
        ldsm4(B1, uBg + boh[1]);
#pragma unroll
        for (int j = 0; j < 4; j++) {
            const uint32_t* Bx = (j < 2) ? B0 : B1;
            uint32_t bp[2] = { Bx[j & 1], Bx[2 + (j & 1)] };
#pragma unroll
            for (int i = 0; i < 2; i++) {
                mma16816(cg[i][j], ah[i], bp);
                mma16816(cg[i][j], al[i], bp);
            }
        }
        // gate lo: term ah*bl
        ldsm4(B0, uBg + bol[0]);
        ldsm4(B1, uBg + bol[1]);
#pragma unroll
        for (int j = 0; j < 4; j++) {
            const uint32_t* Bx = (j < 2) ? B0 : B1;
            uint32_t bp[2] = { Bx[j & 1], Bx[2 + (j & 1)] };
#pragma unroll
            for (int i = 0; i < 2; i++)
                mma16816(cg[i][j], ah[i], bp);
        }
        // up hi
        ldsm4(B0, uBu + boh[0]);
        ldsm4(B1, uBu + boh[1]);
#pragma unroll
        for (int j = 0; j < 4; j++) {
            const uint32_t* Bx = (j < 2) ? B0 : B1;
            uint32_t bp[2] = { Bx[j & 1], Bx[2 + (j & 1)] };
#pragma unroll
            for (int i = 0; i < 2; i++) {
                mma16816(cu[i][j], ah[i], bp);
                mma16816(cu[i][j], al[i], bp);
            }
        }
        // up lo
        ldsm4(B0, uBu + bol[0]);
        ldsm4(B1, uBu + bol[1]);
#pragma unroll
        for (int j = 0; j < 4; j++) {
            const uint32_t* Bx = (j < 2) ? B0 : B1;
            uint32_t bp[2] = { Bx[j & 1], Bx[2 + (j & 1)] };
#pragma unroll
            for (int i = 0; i < 2; i++)
                mma16816(cu[i][j], ah[i], bp);
        }
    };

    const int NC = HD / 16;  // 64
    gload(0); gstore(0);
    __syncthreads();
    for (int ci = 0; ci < NC; ci++) {
        if (ci + 1 < NC) gload(ci + 1);
        compute(ci & 1);
        if (ci + 1 < NC) {
            gstore((ci + 1) & 1);
            __syncthreads();
        }
    }

    // ---- epilogue: silu(g)*u -> d_g fp32 ----
    int fr = lane >> 2, fc = lane & 3;
#pragma unroll
    for (int i = 0; i < 2; i++)
#pragma unroll
        for (int h = 0; h < 2; h++) {
            int row = wm + i * 16 + fr + h * 8;
            if (row < rows) {
                size_t rb = (size_t)(off + m0 + row) * FD + n0 + wn + fc * 2;
#pragma unroll
                for (int j = 0; j < 4; j++) {
                    float g0 = cg[i][j][h * 2 + 0], g1 = cg[i][j][h * 2 + 1];
                    float u0 = cu[i][j][h * 2 + 0], u1 = cu[i][j][h * 2 + 1];
                    float v0 = g0 / (1.f + expf(-g0)) * u0;
                    float v1 = g1 / (1.f + expf(-g1)) * u1;
                    *(float2*)(d_g + rb + j * 8) = make_float2(v0, v1);
                }
            }
        }
}

// ---------------- stage B: Y = G @ Wd, CTA 128x64, double-buffered, ldmatrix ----------------
__global__ __launch_bounds__(256) void gemm_d_mma(const float* __restrict__ Wd)
{
    __shared__ __align__(16) char sA[2][ATILE];
    __shared__ __align__(16) char sB[2][BTILE];

    int e = blockIdx.z;
    int n = d_count[e];
    int m0 = blockIdx.y * 128;
    if (m0 >= n) return;
    int off = d_offset[e];
    int n0 = blockIdx.x * 64;
    int rows = min(128, n - m0);

    int tid = threadIdx.x, lane = tid & 31, wid = tid >> 5;
    const float* wd = Wd + (size_t)e * FD * HD;

    int bn = tid & 63, bkq = tid >> 6;
    int wm = (wid & 3) * 32, wn = (wid >> 2) * 32;

    int ar0 = tid >> 2, ac0 = tid & 3;
    int ar1 = ar0 + 64, ac1 = ac0;
    int am0 = min(ar0, rows - 1), am1 = min(ar1, rows - 1);
    const float* as0 = d_g + (size_t)(off + m0 + am0) * FD + ac0 * 4;
    const float* as1 = d_g + (size_t)(off + m0 + am1) * FD + ac1 * 4;

    uint32_t sth0 = swz(ar0, ac0 >> 1) + (ac0 & 1) * 8;
    uint32_t stl0 = swz(ar0, 2 + (ac0 >> 1)) + (ac0 & 1) * 8;
    uint32_t sth1 = swz(ar1, ac1 >> 1) + (ac1 & 1) * 8;
    uint32_t stl1 = swz(ar1, 2 + (ac1 >> 1)) + (ac1 & 1) * 8;
    uint32_t bsth = swz(bn, bkq >> 1) + (bkq & 1) * 8;
    uint32_t bstl = swz(bn, 2 + (bkq >> 1)) + (bkq & 1) * 8;

    int lr = lane & 15, lc = lane >> 4;
    uint32_t aoh[2], aol[2], boh[2], bol[2];
#pragma unroll
    for (int i = 0; i < 2; i++) {
        int r = wm + i * 16 + lr;
        aoh[i] = swz(r, lc);
        aol[i] = swz(r, 2 + lc);
    }
#pragma unroll
    for (int jj = 0; jj < 2; jj++) {
        int r = wn + jj * 16 + lr;
        boh[jj] = swz(r, lc);
        bol[jj] = swz(r, 2 + lc);
    }

    float4 rav[2], rbv;
    auto gload = [&](int ci) {
        int k0 = ci * 16;
        rav[0] = *(const float4*)(as0 + k0);
        rav[1] = *(const float4*)(as1 + k0);
        int kb = k0 + bkq * 4;
        rbv.x = wd[(size_t)(kb + 0) * HD + n0 + bn];
        rbv.y = wd[(size_t)(kb + 1) * HD + n0 + bn];
        rbv.z = wd[(size_t)(kb + 2) * HD + n0 + bn];
        rbv.w = wd[(size_t)(kb + 3) * HD + n0 + bn];
    };
    auto gstore = [&](int buf) {
        uint2 hi, lo;
        split4(rav[0], hi, lo);
        *(uint2*)(sA[buf] + sth0) = hi;
        *(uint2*)(sA[buf] + stl0) = lo;
        split4(rav[1], hi, lo);
        *(uint2*)(sA[buf] + sth1) = hi;
        *(uint2*)(sA[buf] + stl1) = lo;
        split4(rbv, hi, lo);
        *(uint2*)(sB[buf] + bsth) = hi;
        *(uint2*)(sB[buf] + bstl) = lo;
    };

    float cc[2][4][4];
#pragma unroll
    for (int i = 0; i < 2; i++)
#pragma unroll
        for (int j = 0; j < 4; j++)
#pragma unroll
            for (int q = 0; q < 4; q++) cc[i][j][q] = 0.f;

    auto compute = [&](int buf) {
        uint32_t uA = smem_u32(sA[buf]);
        uint32_t uB = smem_u32(sB[buf]);
        uint32_t ah[2][4], al[2][4];
        ldsm4(ah[0], uA + aoh[0]);
        ldsm4(ah[1], uA + aoh[1]);
        ldsm4(al[0], uA + aol[0]);
        ldsm4(al[1], uA + aol[1]);
        uint32_t B0[4], B1[4];
        ldsm4(B0, uB + boh[0]);
        ldsm4(B1, uB + boh[1]);
#pragma unroll
        for (int j = 0; j < 4; j++) {
            const uint32_t* Bx = (j < 2) ? B0 : B1;
            uint32_t bp[2] = { Bx[j & 1], Bx[2 + (j & 1)] };
#pragma unroll
            for (int i = 0; i < 2; i++) {
                mma16816(cc[i][j], ah[i], bp);
                mma16816(cc[i][j], al[i], bp);
            }
        }
        ldsm4(B0, uB + bol[0]);
        ldsm4(B1, uB + bol[1]);
#pragma unroll
        for (int j = 0; j < 4; j++) {
            const uint32_t* Bx = (j < 2) ? B0 : B1;
            uint32_t bp[2] = { Bx[j & 1], Bx[2 + (j & 1)] };
#pragma unroll
            for (int i = 0; i < 2; i++)
                mma16816(cc[i][j], ah[i], bp);
        }
    };

    const int NC = FD / 16;  // 128
    gload(0); gstore(0);
    __syncthreads();
    for (int ci = 0; ci < NC; ci++) {
        if (ci + 1 < NC) gload(ci + 1);
        compute(ci & 1);
        if (ci + 1 < NC) {
            gstore((ci + 1) & 1);
            __syncthreads();
        }
    }

    int fr = lane >> 2, fc = lane & 3;
#pragma unroll
    for (int i = 0; i < 2; i++)
#pragma unroll
        for (int h = 0; h < 2; h++) {
            int row = wm + i * 16 + fr + h * 8;
            if (row < rows) {
                size_t rb = (size_t)(off + m0 + row) * HD + n0 + wn + fc * 2;
#pragma unroll
                for (int j = 0; j < 4; j++)
                    *(float2*)(d_y + rb + j * 8) = make_float2(cc[i][j][h * 2 + 0], cc[i][j][h * 2 + 1]);
            }
        }
}

// ---------------- combine (proven R1) ----------------
__global__ __launch_bounds__(256) void combine_kernel(float* __restrict__ out)
{
    int t = blockIdx.x;
    int s0 = d_slot[t * 2 + 0], s1 = d_slot[t * 2 + 1];
    float w0 = d_tw[t * 2 + 0], w1 = d_tw[t * 2 + 1];
    const float* y0 = d_y + (size_t)s0 * HD;
    const float* y1 = d_y + (size_t)s1 * HD;
    float* o = out + (size_t)t * HD;
    for (int h = threadIdx.x * 4; h < HD; h += blockDim.x * 4) {
        float4 a = *(const float4*)(y0 + h);
        float4 b = *(const float4*)(y1 + h);
        *(float4*)(o + h) = make_float4(w0 * a.x + w1 * b.x, w0 * a.y + w1 * b.y,
                                        w0 * a.z + w1 * b.z, w0 * a.w + w1 * b.w);
    }
}

// ---------------- launch ----------------
extern "C" void kernel_launch(void* const* d_in, const int* in_sizes, int n_in,
                              void* d_out, int out_size)
{
    const float* x  = (const float*)d_in[0];
    const float* gw = (const float*)d_in[1];
    const float* Wg = (const float*)d_in[2];
    const float* Wu = (const float*)d_in[3];
    const float* Wd = (const float*)d_in[4];

    float* out = (float*)d_out;
    const int OUT_ELEMS = NT * HD;
    const int LOG_ELEMS = NT * NE;

    float* out_main = nullptr;
    float* out_logits = nullptr;
    if (out_size >= OUT_ELEMS + LOG_ELEMS) { out_main = out; out_logits = out + (size_t)OUT_ELEMS; }
    else if (out_size >= OUT_ELEMS)        { out_main = out; }
    else                                   { out_logits = out; }

    zero_counts_kernel<<<1, 32>>>();
    router_kernel<<<NT / 8, 256>>>(x, gw, out_logits);
    scan_kernel<<<1, 1>>>();
    remap_kernel<<<NE, 256>>>();

    if (out_main) {
        gemm_gu_mma<<<dim3(FD / 64, NT / 128, NE), 256>>>(x, Wg, Wu);
        gemm_d_mma<<<dim3(HD / 64, NT / 128, NE), 256>>>(Wd);
        combine_kernel<<<NT, 256>>>(out_main);
    }
}

// round 17
// speedup vs baseline: 1.9940x; 1.0822x over previous
#include <cuda_runtime.h>
#include <cuda_bf16.h>
#include <cstdint>

#define NE 8
#define HD 1024
#define FD 2048
#define NT 8192
#define NSLOT (NT*2)

// ---------------- device scratch ----------------
__device__ int   d_count[NE];
__device__ int   d_offset[NE];
__device__ int   d_etok[NE * NT];
__device__ int   d_slot[NSLOT];
__device__ float d_tw[NSLOT];

__device__ __nv_bfloat16 d_xh[(size_t)NT * HD];
__device__ __nv_bfloat16 d_xl[(size_t)NT * HD];
__device__ __nv_bfloat16 d_wgh[(size_t)NE * HD * FD];   // [E][F][H] K-major
__device__ __nv_bfloat16 d_wgl[(size_t)NE * HD * FD];
__device__ __nv_bfloat16 d_wuh[(size_t)NE * HD * FD];
__device__ __nv_bfloat16 d_wul[(size_t)NE * HD * FD];
__device__ __nv_bfloat16 d_wdh[(size_t)NE * FD * HD];   // [E][H][F] K-major
__device__ __nv_bfloat16 d_wdl[(size_t)NE * FD * HD];
__device__ __nv_bfloat16 d_gh[(size_t)NSLOT * FD];
__device__ __nv_bfloat16 d_gl[(size_t)NSLOT * FD];
__device__ float d_y[(size_t)NSLOT * HD];

// ---------------- helpers ----------------
__device__ __forceinline__ uint32_t smem_u32(const void* p) {
    uint32_t a;
    asm("{ .reg .u64 t; cvta.to.shared.u64 t, %1; cvt.u32.u64 %0, t; }" : "=r"(a) : "l"(p));
    return a;
}
__device__ __forceinline__ void cpa16(uint32_t dst, const void* src) {
    asm volatile("cp.async.cg.shared.global [%0], [%1], 16;\n" :: "r"(dst), "l"(src));
}
#define CP_COMMIT() asm volatile("cp.async.commit_group;")
#define CP_WAIT0()  asm volatile("cp.async.wait_group 0;")

__device__ __forceinline__ void ldsm4(uint32_t* r, uint32_t addr) {
    asm volatile("ldmatrix.sync.aligned.m8n8.x4.shared.b16 {%0,%1,%2,%3}, [%4];"
        : "=r"(r[0]), "=r"(r[1]), "=r"(r[2]), "=r"(r[3]) : "r"(addr));
}
__device__ __forceinline__ void mma16816(float* d, const uint32_t* a, const uint32_t* b) {
    asm volatile("mma.sync.aligned.m16n8k16.row.col.f32.bf16.bf16.f32 "
        "{%0,%1,%2,%3}, {%4,%5,%6,%7}, {%8,%9}, {%0,%1,%2,%3};"
        : "+f"(d[0]), "+f"(d[1]), "+f"(d[2]), "+f"(d[3])
        : "r"(a[0]), "r"(a[1]), "r"(a[2]), "r"(a[3]), "r"(b[0]), "r"(b[1]));
}
__device__ __forceinline__ uint32_t pack2(__nv_bfloat16 a, __nv_bfloat16 b) {
    return (uint32_t)__bfloat16_as_ushort(a) | ((uint32_t)__bfloat16_as_ushort(b) << 16);
}
__device__ __forceinline__ void split_bf16(float v, __nv_bfloat16& h, __nv_bfloat16& l) {
    h = __float2bfloat16(v);
    l = __float2bfloat16(v - __bfloat162float(h));
}

// 64B rows: chunks [hi k0-7 | hi k8-15 | lo k0-7 | lo k8-15], chunk XOR-swizzled by (row>>1)&3.
__device__ __forceinline__ uint32_t swz(int row, int chunk) {
    return (uint32_t)(row * 64 + ((chunk ^ ((row >> 1) & 3)) * 16));
}
#define ATILE (128 * 64)   // 8192
#define BTILE (64 * 64)    // 4096

// ---------------- routing (proven R1) ----------------
__global__ void zero_counts_kernel() {
    if (threadIdx.x < NE) d_count[threadIdx.x] = 0;
}
__global__ void scan_kernel() {
    int off = 0;
    for (int e = 0; e < NE; e++) { d_offset[e] = off; off += d_count[e]; }
}
__global__ void remap_kernel() {
    int e = blockIdx.x;
    int n = d_count[e], off = d_offset[e];
    for (int p = threadIdx.x; p < n; p += blockDim.x)
        d_slot[d_etok[e * NT + p]] = off + p;
}

__global__ __launch_bounds__(256) void router_kernel(
    const float* __restrict__ x, const float* __restrict__ gw,
    float* __restrict__ logits_out)
{
    __shared__ float gws[NE * HD];
    for (int i = threadIdx.x; i < NE * HD; i += blockDim.x) gws[i] = gw[i];
    __syncthreads();

    int warp = threadIdx.x >> 5, lane = threadIdx.x & 31;
    int t = blockIdx.x * 8 + warp;
    if (t >= NT) return;

    const float* xr = x + (size_t)t * HD;
    float acc[NE];
#pragma unroll
    for (int e = 0; e < NE; e++) acc[e] = 0.f;
    for (int h = lane * 4; h < HD; h += 128) {
        float4 xv = *(const float4*)(xr + h);
#pragma unroll
        for (int e = 0; e < NE; e++) {
            float4 wv = *(const float4*)(&gws[e * HD + h]);
            acc[e] += xv.x * wv.x + xv.y * wv.y + xv.z * wv.z + xv.w * wv.w;
        }
    }
#pragma unroll
    for (int e = 0; e < NE; e++)
        for (int o = 16; o > 0; o >>= 1)
            acc[e] += __shfl_xor_sync(0xffffffffu, acc[e], o);

    if (lane == 0) {
        if (logits_out) {
#pragma unroll
            for (int e = 0; e < NE; e++) logits_out[(size_t)t * NE + e] = acc[e];
        }
        float m = acc[0];
#pragma unroll
        for (int e = 1; e < NE; e++) m = fmaxf(m, acc[e]);
        float p[NE];
#pragma unroll
        for (int e = 0; e < NE; e++) p[e] = expf(acc[e] - m);
        int i1 = 0;
#pragma unroll
        for (int e = 1; e < NE; e++) if (p[e] > p[i1]) i1 = e;
        int i2 = (i1 == 0) ? 1 : 0;
#pragma unroll
        for (int e = 0; e < NE; e++) if (e != i1 && p[e] > p[i2]) i2 = e;
        float s2 = p[i1] + p[i2];
        d_tw[t * 2 + 0] = p[i1] / s2;
        d_tw[t * 2 + 1] = p[i2] / s2;
        int pos = atomicAdd(&d_count[i1], 1);
        d_etok[i1 * NT + pos] = t * 2 + 0;
        pos = atomicAdd(&d_count[i2], 1);
        d_etok[i2 * NT + pos] = t * 2 + 1;
    }
}

// ---------------- prep: x split ----------------
__global__ __launch_bounds__(256) void convert_x_kernel(const float* __restrict__ x) {
    size_t i4 = ((size_t)blockIdx.x * blockDim.x + threadIdx.x) * 4;
    if (i4 >= (size_t)NT * HD) return;
    float4 v = *(const float4*)(x + i4);
    __nv_bfloat16 h0, l0, h1, l1, h2, l2, h3, l3;
    split_bf16(v.x, h0, l0); split_bf16(v.y, h1, l1);
    split_bf16(v.z, h2, l2); split_bf16(v.w, h3, l3);
    uint2 ph, pl;
    ph.x = pack2(h0, h1); ph.y = pack2(h2, h3);
    pl.x = pack2(l0, l1); pl.y = pack2(l2, l3);
    *(uint2*)(d_xh + i4) = ph;
    *(uint2*)(d_xl + i4) = pl;
}

// prep: transpose + split. W [E][R][C] fp32 -> [E][C][R] bf16 hi/lo.
// Destination chosen in DEVICE code (R8-proven: never pass __device__ symbols from host).
__global__ __launch_bounds__(256) void transpose_split_kernel(
    const float* __restrict__ W, int which, int R, int C)
{
    __nv_bfloat16* oh;
    __nv_bfloat16* ol;
    if (which == 0)      { oh = d_wgh; ol = d_wgl; }
    else if (which == 1) { oh = d_wuh; ol = d_wul; }
    else                 { oh = d_wdh; ol = d_wdl; }

    __shared__ float t[32][33];
    int e = blockIdx.z;
    const float* w = W + (size_t)e * R * C;
    __nv_bfloat16* ph = oh + (size_t)e * R * C;
    __nv_bfloat16* pl = ol + (size_t)e * R * C;
    int c0 = blockIdx.x * 32, r0 = blockIdx.y * 32;
    int tx = threadIdx.x, ty = threadIdx.y;
#pragma unroll
    for (int i = 0; i < 4; i++)
        t[ty + 8 * i][tx] = w[(size_t)(r0 + ty + 8 * i) * C + c0 + tx];
    __syncthreads();
#pragma unroll
    for (int i = 0; i < 4; i++) {
        float v = t[tx][ty + 8 * i];
        __nv_bfloat16 h, l;
        split_bf16(v, h, l);
        size_t o = (size_t)(c0 + ty + 8 * i) * R + r0 + tx;
        ph[o] = h; pl[o] = l;
    }
}

// ---------------- stage A: G = silu(X Wg)*(X Wu), CTA 128x64, cp.async + ldmatrix ----------------
__global__ __launch_bounds__(256, 2) void gemm_gu_mma(void)
{
    __shared__ __align__(16) char sA[2][ATILE];
    __shared__ __align__(16) char sBg[2][BTILE];
    __shared__ __align__(16) char sBu[2][BTILE];
    __shared__ int toks[128];

    int e = blockIdx.z;
    int n = d_count[e];
    int m0 = blockIdx.y * 128;
    if (m0 >= n) return;
    int off = d_offset[e];
    int n0 = blockIdx.x * 64;
    int rows = min(128, n - m0);

    int tid = threadIdx.x, lane = tid & 31, wid = tid >> 5;
    if (tid < 128) toks[tid] = d_etok[e * NT + m0 + min(tid, rows - 1)] >> 1;
    __syncthreads();

    const __nv_bfloat16* wgh = d_wgh + (size_t)e * FD * HD;
    const __nv_bfloat16* wgl = d_wgl + (size_t)e * FD * HD;
    const __nv_bfloat16* wuh = d_wuh + (size_t)e * FD * HD;
    const __nv_bfloat16* wul = d_wul + (size_t)e * FD * HD;

    int wm = (wid & 3) * 32, wn = (wid >> 2) * 32;

    // A cp.async assignment: idx in {tid, tid+256}: row = idx>>2, part = idx&3 (chunk == part)
    int ar0 = tid >> 2, ap0 = tid & 3;
    int ar1 = (tid + 256) >> 2, ap1 = tid & 3;
    uint32_t adst0 = swz(ar0, ap0), adst1 = swz(ar1, ap1);
    // B assignment: idx = tid: row = tid>>2 (0..63), part = tid&3
    int br = tid >> 2, bp = tid & 3;
    uint32_t bdst = swz(br, bp);

    auto load = [&](int ci, int buf) {
        int k0 = ci * 16;
        {
            const __nv_bfloat16* s0 = (ap0 < 2 ? d_xh : d_xl) + (size_t)toks[ar0] * HD + k0 + (ap0 & 1) * 8;
            const __nv_bfloat16* s1 = (ap1 < 2 ? d_xh : d_xl) + (size_t)toks[ar1] * HD + k0 + (ap1 & 1) * 8;
            cpa16(smem_u32(sA[buf]) + adst0, s0);
            cpa16(smem_u32(sA[buf]) + adst1, s1);
        }
        {
            size_t go = (size_t)(n0 + br) * HD + k0 + (bp & 1) * 8;
            const __nv_bfloat16* sg = (bp < 2 ? wgh : wgl) + go;
            const __nv_bfloat16* su = (bp < 2 ? wuh : wul) + go;
            cpa16(smem_u32(sBg[buf]) + bdst, sg);
            cpa16(smem_u32(sBu[buf]) + bdst, su);
        }
    };

    // ldmatrix per-thread addresses
    int lr = lane & 15, lc = lane >> 4;
    uint32_t aoh[2], aol[2], boh[2], bol[2];
#pragma unroll
    for (int i = 0; i < 2; i++) {
        int r = wm + i * 16 + lr;
        aoh[i] = swz(r, lc);
        aol[i] = swz(r, 2 + lc);
    }
#pragma unroll
    for (int jj = 0; jj < 2; jj++) {
        int r = wn + jj * 16 + lr;
        boh[jj] = swz(r, lc);
        bol[jj] = swz(r, 2 + lc);
    }

    float cg[2][4][4], cu[2][4][4];
#pragma unroll
    for (int i = 0; i < 2; i++)
#pragma unroll
        for (int j = 0; j < 4; j++)
#pragma unroll
            for (int q = 0; q < 4; q++) { cg[i][j][q] = 0.f; cu[i][j][q] = 0.f; }

    auto compute = [&](int buf) {
        uint32_t uA = smem_u32(sA[buf]);
        uint32_t uBg = smem_u32(sBg[buf]);
        uint32_t uBu = smem_u32(sBu[buf]);
        uint32_t ah[2][4], al[2][4];
        ldsm4(ah[0], uA + aoh[0]);
        ldsm4(ah[1], uA + aoh[1]);
        ldsm4(al[0], uA + aol[0]);
        ldsm4(al[1], uA + aol[1]);
        uint32_t B0[4], B1[4];
        ldsm4(B0, uBg + boh[0]);
        ldsm4(B1, uBg + boh[1]);
#pragma unroll
        for (int j = 0; j < 4; j++) {
            const uint32_t* Bx = (j < 2) ? B0 : B1;
            uint32_t bpv[2] = { Bx[j & 1], Bx[2 + (j & 1)] };
#pragma unroll
            for (int i = 0; i < 2; i++) {
                mma16816(cg[i][j], ah[i], bpv);
                mma16816(cg[i][j], al[i], bpv);
            }
        }
        ldsm4(B0, uBg + bol[0]);
        ldsm4(B1, uBg + bol[1]);
#pragma unroll
        for (int j = 0; j < 4; j++) {
            const uint32_t* Bx = (j < 2) ? B0 : B1;
            uint32_t bpv[2] = { Bx[j & 1], Bx[2 + (j & 1)] };
#pragma unroll
            for (int i = 0; i < 2; i++)
                mma16816(cg[i][j], ah[i], bpv);
        }
        ldsm4(B0, uBu + boh[0]);
        ldsm4(B1, uBu + boh[1]);
#pragma unroll
        for (int j = 0; j < 4; j++) {
            const uint32_t* Bx = (j < 2) ? B0 : B1;
            uint32_t bpv[2] = { Bx[j & 1], Bx[2 + (j & 1)] };
#pragma unroll
            for (int i = 0; i < 2; i++) {
                mma16816(cu[i][j], ah[i], bpv);
                mma16816(cu[i][j], al[i], bpv);
            }
        }
        ldsm4(B0, uBu + bol[0]);
        ldsm4(B1, uBu + bol[1]);
#pragma unroll
        for (int j = 0; j < 4; j++) {
            const uint32_t* Bx = (j < 2) ? B0 : B1;
            uint32_t bpv[2] = { Bx[j & 1], Bx[2 + (j & 1)] };
#pragma unroll
            for (int i = 0; i < 2; i++)
                mma16816(cu[i][j], ah[i], bpv);
        }
    };

    const int NC = HD / 16;  // 64
    load(0, 0); CP_COMMIT();
    for (int ci = 0; ci < NC; ci++) {
        CP_WAIT0();
        __syncthreads();
        if (ci + 1 < NC) { load(ci + 1, (ci + 1) & 1); CP_COMMIT(); }
        compute(ci & 1);
    }

    // ---- epilogue: silu(g)*u -> bf16 hi/lo ----
    int fr = lane >> 2, fc = lane & 3;
#pragma unroll
    for (int i = 0; i < 2; i++)
#pragma unroll
        for (int h = 0; h < 2; h++) {
            int row = wm + i * 16 + fr + h * 8;
            if (row < rows) {
                size_t rb = (size_t)(off + m0 + row) * FD + n0 + wn + fc * 2;
#pragma unroll
                for (int j = 0; j < 4; j++) {
                    float g0 = cg[i][j][h * 2 + 0], g1 = cg[i][j][h * 2 + 1];
                    float u0 = cu[i][j][h * 2 + 0], u1 = cu[i][j][h * 2 + 1];
                    float v0 = g0 / (1.f + expf(-g0)) * u0;
                    float v1 = g1 / (1.f + expf(-g1)) * u1;
                    __nv_bfloat16 h0, l0, h1, l1;
                    split_bf16(v0, h0, l0);
                    split_bf16(v1, h1, l1);
                    *(uint32_t*)(d_gh + rb + j * 8) = pack2(h0, h1);
                    *(uint32_t*)(d_gl + rb + j * 8) = pack2(l0, l1);
                }
            }
        }
}

// ---------------- stage B: Y = G @ Wd, CTA 128x64, cp.async + ldmatrix ----------------
__global__ __launch_bounds__(256, 2) void gemm_d_mma(void)
{
    __shared__ __align__(16) char sA[2][ATILE];
    __shared__ __align__(16) char sB[2][BTILE];

    int e = blockIdx.z;
    int n = d_count[e];
    int m0 = blockIdx.y * 128;
    if (m0 >= n) return;
    int off = d_offset[e];
    int n0 = blockIdx.x * 64;
    int rows = min(128, n - m0);

    int tid = threadIdx.x, lane = tid & 31, wid = tid >> 5;
    const __nv_bfloat16* wdh = d_wdh + (size_t)e * HD * FD;
    const __nv_bfloat16* wdl = d_wdl + (size_t)e * HD * FD;

    int wm = (wid & 3) * 32, wn = (wid >> 2) * 32;

    int ar0 = tid >> 2, ap0 = tid & 3;
    int ar1 = (tid + 256) >> 2, ap1 = tid & 3;
    uint32_t adst0 = swz(ar0, ap0), adst1 = swz(ar1, ap1);
    size_t arow0 = (size_t)(off + m0 + min(ar0, rows - 1)) * FD;
    size_t arow1 = (size_t)(off + m0 + min(ar1, rows - 1)) * FD;
    int br = tid >> 2, bp = tid & 3;
    uint32_t bdst = swz(br, bp);

    auto load = [&](int ci, int buf) {
        int k0 = ci * 16;
        const __nv_bfloat16* s0 = (ap0 < 2 ? d_gh : d_gl) + arow0 + k0 + (ap0 & 1) * 8;
        const __nv_bfloat16* s1 = (ap1 < 2 ? d_gh : d_gl) + arow1 + k0 + (ap1 & 1) * 8;
        cpa16(smem_u32(sA[buf]) + adst0, s0);
        cpa16(smem_u32(sA[buf]) + adst1, s1);
        size_t go = (size_t)(n0 + br) * FD + k0 + (bp & 1) * 8;
        const __nv_bfloat16* sb = (bp < 2 ? wdh : wdl) + go;
        cpa16(smem_u32(sB[buf]) + bdst, sb);
    };

    int lr = lane & 15, lc = lane >> 4;
    uint32_t aoh[2], aol[2], boh[2], bol[2];
#pragma unroll
    for (int i = 0; i < 2; i++) {
        int r = wm + i * 16 + lr;
        aoh[i] = swz(r, lc);
        aol[i] = swz(r, 2 + lc);
    }
#pragma unroll
    for (int jj = 0; jj < 2; jj++) {
        int r = wn + jj * 16 + lr;
        boh[jj] = swz(r, lc);
        bol[jj] = swz(r, 2 + lc);
    }

    float cc[2][4][4];
#pragma unroll
    for (int i = 0; i < 2; i++)
#pragma unroll
        for (int j = 0; j < 4; j++)
#pragma unroll
            for (int q = 0; q < 4; q++) cc[i][j][q] = 0.f;

    auto compute = [&](int buf) {
        uint32_t uA = smem_u32(sA[buf]);
        uint32_t uB = smem_u32(sB[buf]);
        uint32_t ah[2][4], al[2][4];
        ldsm4(ah[0], uA + aoh[0]);
        ldsm4(ah[1], uA + aoh[1]);
        ldsm4(al[0], uA + aol[0]);
        ldsm4(al[1], uA + aol[1]);
        uint32_t B0[4], B1[4];
        ldsm4(B0, uB + boh[0]);
        ldsm4(B1, uB + boh[1]);
#pragma unroll
        for (int j = 0; j < 4; j++) {
            const uint32_t* Bx = (j < 2) ? B0 : B1;
            uint32_t bpv[2] = { Bx[j & 1], Bx[2 + (j & 1)] };
#pragma unroll
            for (int i = 0; i < 2; i++) {
                mma16816(cc[i][j], ah[i], bpv);
                mma16816(cc[i][j], al[i], bpv);
            }
        }
        ldsm4(B0, uB + bol[0]);
        ldsm4(B1, uB + bol[1]);
#pragma unroll
        for (int j = 0; j < 4; j++) {
            const uint32_t* Bx = (j < 2) ? B0 : B1;
            uint32_t bpv[2] = { Bx[j & 1], Bx[2 + (j & 1)] };
#pragma unroll
            for (int i = 0; i < 2; i++)
                mma16816(cc[i][j], ah[i], bpv);
        }
    };

    const int NC = FD / 16;  // 128
    load(0, 0); CP_COMMIT();
    for (int ci = 0; ci < NC; ci++) {
        CP_WAIT0();
        __syncthreads();
        if (ci + 1 < NC) { load(ci + 1, (ci + 1) & 1); CP_COMMIT(); }
        compute(ci & 1);
    }

    int fr = lane >> 2, fc = lane & 3;
#pragma unroll
    for (int i = 0; i < 2; i++)
#pragma unroll
        for (int h = 0; h < 2; h++) {
            int row = wm + i * 16 + fr + h * 8;
            if (row < rows) {
                size_t rb = (size_t)(off + m0 + row) * HD + n0 + wn + fc * 2;
#pragma unroll
                for (int j = 0; j < 4; j++)
                    *(float2*)(d_y + rb + j * 8) = make_float2(cc[i][j][h * 2 + 0], cc[i][j][h * 2 + 1]);
            }
        }
}

// ---------------- combine (proven R1) ----------------
__global__ __launch_bounds__(256) void combine_kernel(float* __restrict__ out)
{
    int t = blockIdx.x;
    int s0 = d_slot[t * 2 + 0], s1 = d_slot[t * 2 + 1];
    float w0 = d_tw[t * 2 + 0], w1 = d_tw[t * 2 + 1];
    const float* y0 = d_y + (size_t)s0 * HD;
    const float* y1 = d_y + (size_t)s1 * HD;
    float* o = out + (size_t)t * HD;
    for (int h = threadIdx.x * 4; h < HD; h += blockDim.x * 4) {
        float4 a = *(const float4*)(y0 + h);
        float4 b = *(const float4*)(y1 + h);
        *(float4*)(o + h) = make_float4(w0 * a.x + w1 * b.x, w0 * a.y + w1 * b.y,
                                        w0 * a.z + w1 * b.z, w0 * a.w + w1 * b.w);
    }
}

// ---------------- launch ----------------
extern "C" void kernel_launch(void* const* d_in, const int* in_sizes, int n_in,
                              void* d_out, int out_size)
{
    const float* x  = (const float*)d_in[0];
    const float* gw = (const float*)d_in[1];
    const float* Wg = (const float*)d_in[2];
    const float* Wu = (const float*)d_in[3];
    const float* Wd = (const float*)d_in[4];

    float* out = (float*)d_out;
    const int OUT_ELEMS = NT * HD;
    const int LOG_ELEMS = NT * NE;

    float* out_main = nullptr;
    float* out_logits = nullptr;
    if (out_size >= OUT_ELEMS + LOG_ELEMS) { out_main = out; out_logits = out + (size_t)OUT_ELEMS; }
    else if (out_size >= OUT_ELEMS)        { out_main = out; }
    else                                   { out_logits = out; }

    zero_counts_kernel<<<1, 32>>>();
    router_kernel<<<NT / 8, 256>>>(x, gw, out_logits);
    scan_kernel<<<1, 1>>>();
    remap_kernel<<<NE, 256>>>();

    if (out_main) {
        convert_x_kernel<<<(NT * HD / 4 + 255) / 256, 256>>>(x);
        dim3 tb(32, 8);
        transpose_split_kernel<<<dim3(FD / 32, HD / 32, NE), tb>>>(Wg, 0, HD, FD);
        transpose_split_kernel<<<dim3(FD / 32, HD / 32, NE), tb>>>(Wu, 1, HD, FD);
        transpose_split_kernel<<<dim3(HD / 32, FD / 32, NE), tb>>>(Wd, 2, FD, HD);

        gemm_gu_mma<<<dim3(FD / 64, NT / 128, NE), 256>>>();
        gemm_d_mma<<<dim3(HD / 64, NT / 128, NE), 256>>>();
        combine_kernel<<<NT, 256>>>(out_main);
    }
}